// round 11
// baseline (speedup 1.0000x reference)
#include <cuda_runtime.h>
#include <cuda_bf16.h>
#include <cstdint>

typedef unsigned long long ull;

// ---------------- problem constants ----------------
#define BATCH 64
#define DIN   176
#define HID   512
#define G4    2048          // 4*HID
#define T_ENC 1025          // 1 + 1024
#define T_DEC 1023          // TTGT - 1
#define MROWS_MAX (BATCH * T_ENC)   // 65600
#define MD_ROWS   (BATCH * T_DEC)   // 65472

// ---------------- scratch (static device globals; no cudaMalloc allowed) ----
__device__ float g_gx[(size_t)MROWS_MAX * G4];     // per-layer gx (fp32)
#define ABUF_ROWS (MROWS_MAX + 128)
__device__ __nv_bfloat16 g_AH[(size_t)ABUF_ROWS * 512];   // A operand hi
__device__ __nv_bfloat16 g_AL[(size_t)ABUF_ROWS * 512];   // A operand lo
#define MBUF_ROWS (MD_ROWS + 128)
__device__ __nv_bfloat16 g_MH[(size_t)MBUF_ROWS * 256];   // hmid hi
__device__ __nv_bfloat16 g_ML[(size_t)MBUF_ROWS * 256];   // hmid lo
__device__ __nv_bfloat16 g_WHb[2048 * 512];               // W operand hi
__device__ __nv_bfloat16 g_WLb[2048 * 512];               // W operand lo
__device__ float g_hpub[2 * BATCH * HID];                 // packed (hi,lo) bf16 pairs
__device__ float g_hT0[BATCH * HID], g_cT0[BATCH * HID];
__device__ float g_hT1[BATCH * HID], g_cT1[BATCH * HID];
__device__ float g_hTd[BATCH * HID], g_cTd[BATCH * HID];
__device__ unsigned g_bar[4];

// ---------------- helpers ----------------
__device__ __forceinline__ void bf16_split(float v, __nv_bfloat16& hi, __nv_bfloat16& lo) {
    hi = __float2bfloat16(v);
    lo = __float2bfloat16(v - __bfloat162float(hi));
}

__device__ __forceinline__ uint32_t smem_to_u32(const void* p) {
    uint32_t a;
    asm("{ .reg .u64 t; cvta.to.shared.u64 t, %1; cvt.u32.u64 %0, t; }" : "=r"(a) : "l"(p));
    return a;
}

// HMMA m16n8k16 bf16 (non-arch-gated PTX; runs on sm_103 base target)
__device__ __forceinline__ void mma16816(float* d, const uint32_t* a, const uint32_t* b) {
    asm volatile(
        "mma.sync.aligned.m16n8k16.row.col.f32.bf16.bf16.f32 "
        "{%0,%1,%2,%3}, {%4,%5,%6,%7}, {%8,%9}, {%0,%1,%2,%3};"
        : "+f"(d[0]), "+f"(d[1]), "+f"(d[2]), "+f"(d[3])
        : "r"(a[0]), "r"(a[1]), "r"(a[2]), "r"(a[3]), "r"(b[0]), "r"(b[1]));
}

// cp.async 16B (LDGSTS; sm_80 PTX, non-gated)
__device__ __forceinline__ void cpasync16(uint32_t s, const void* g) {
    asm volatile("cp.async.cg.shared.global [%0], [%1], 16;" :: "r"(s), "l"(g));
}
#define CP_COMMIT() asm volatile("cp.async.commit_group;" ::: "memory")
#define CP_WAIT1()  asm volatile("cp.async.wait_group 1;" ::: "memory")

// ---------------- small utility kernels ----------------
__global__ void reset_bar_kernel(unsigned* bar) {
    if (threadIdx.x < 4) bar[threadIdx.x] = 0u;
}

// padded-shifted input -> bf16 hi/lo, layout [b][t][192] (cols 176..191 zero)
__global__ void pad_shift_bf16_kernel(const float* __restrict__ src,
                                      __nv_bfloat16* __restrict__ dH,
                                      __nv_bfloat16* __restrict__ dL,
                                      int Tsrc, int Tpad, int Tcopy) {
    long n = (long)BATCH * Tpad * 192;
    long i = (long)blockIdx.x * blockDim.x + threadIdx.x;
    if (i >= n) return;
    int d = (int)(i % 192);
    long bt = i / 192;
    int t = (int)(bt % Tpad);
    int b = (int)(bt / Tpad);
    float v = (d < DIN && t > 0 && t <= Tcopy) ? src[((long)b * Tsrc + (t - 1)) * DIN + d] : 0.f;
    __nv_bfloat16 hi, lo; bf16_split(v, hi, lo);
    dH[i] = hi; dL[i] = lo;
}

// W (N x K fp32) -> WH/WL (Npad x kpad bf16, zero padded)
__global__ void conv_w_kernel(const float* __restrict__ W,
                              __nv_bfloat16* __restrict__ WH, __nv_bfloat16* __restrict__ WL,
                              int N, int K, int kpad, int Npad) {
    long n = (long)Npad * kpad;
    long i = (long)blockIdx.x * blockDim.x + threadIdx.x;
    if (i >= n) return;
    int row = (int)(i / kpad), c = (int)(i % kpad);
    float v = (row < N && c < K) ? W[(size_t)row * K + c] : 0.f;
    __nv_bfloat16 hi, lo; bf16_split(v, hi, lo);
    WH[i] = hi; WL[i] = lo;
}

__global__ void zero_t0_kernel(float* __restrict__ out) {
    int i = blockIdx.x * blockDim.x + threadIdx.x;
    if (i < BATCH * DIN) {
        int b = i / DIN, d = i % DIN;
        out[(size_t)b * 1024 * DIN + d] = 0.f;
    }
}

// ---------------- HMMA GEMM (cp.async 2-stage pipelined; round-8 proven) ---
#define SOFF_AL  5120
#define SOFF_BH  10240
#define SOFF_BL  12800
#define STG_ELEMS 15360
#define MMA_SMEM_BYTES (2 * STG_ELEMS * 2)   // 61440

__global__ void __launch_bounds__(256)
mma_gemm_kernel(const __nv_bfloat16* __restrict__ AH, const __nv_bfloat16* __restrict__ AL,
                const __nv_bfloat16* __restrict__ WH, const __nv_bfloat16* __restrict__ WL,
                int kpad, int nChunks,
                const float* __restrict__ b1, const float* __restrict__ b2,
                float* __restrict__ Cf, __nv_bfloat16* __restrict__ CH,
                __nv_bfloat16* __restrict__ CL,
                int ldC, int M, int Nreal, int relu, int remapT) {
    extern __shared__ __align__(16) __nv_bfloat16 smbuf[];
    const uint32_t sb = smem_to_u32(smbuf);

    const int tid  = threadIdx.x;
    const int wid  = tid >> 5, lane = tid & 31;
    const int g    = lane >> 2, tg = lane & 3;
    const int m0   = (wid & 3) * 32;
    const int n0   = (wid >> 2) * 32;
    const int row0 = blockIdx.y * 128;
    const int col0 = blockIdx.x * 64;

    const int ar0 = tid >> 2, aseg = tid & 3;
    const int br  = tid >> 2, bseg = tid & 3;

    float d[2][4][4];
#pragma unroll
    for (int mi = 0; mi < 2; mi++)
#pragma unroll
        for (int ni = 0; ni < 4; ni++)
#pragma unroll
            for (int q = 0; q < 4; q++) d[mi][ni][q] = 0.f;

    auto load_chunk = [&](int ch, int stg) {
        const int kbase = ch * 32;
        const uint32_t base = sb + stg * (STG_ELEMS * 2);
#pragma unroll
        for (int i = 0; i < 2; i++) {
            int r = ar0 + i * 64;
            size_t go = (size_t)(row0 + r) * kpad + kbase + aseg * 8;
            uint32_t so = base + (r * 40 + aseg * 8) * 2;
            cpasync16(so, AH + go);
            cpasync16(so + SOFF_AL * 2, AL + go);
        }
        {
            size_t go = (size_t)(col0 + br) * kpad + kbase + bseg * 8;
            uint32_t so = base + (SOFF_BH + br * 40 + bseg * 8) * 2;
            cpasync16(so, WH + go);
            cpasync16(so + (SOFF_BL - SOFF_BH) * 2, WL + go);
        }
    };

    load_chunk(0, 0);
    CP_COMMIT();

    for (int ch = 0; ch < nChunks; ch++) {
        const int cur = ch & 1;
        if (ch + 1 < nChunks) load_chunk(ch + 1, cur ^ 1);
        CP_COMMIT();
        CP_WAIT1();
        __syncthreads();

        const __nv_bfloat16* sAH = smbuf + cur * STG_ELEMS;
        const __nv_bfloat16* sAL = sAH + SOFF_AL;
        const __nv_bfloat16* sBH = smbuf + cur * STG_ELEMS + SOFF_BH;
        const __nv_bfloat16* sBL = smbuf + cur * STG_ELEMS + SOFF_BL;

#pragma unroll
        for (int ks = 0; ks < 2; ks++) {
            const int kb = ks * 16;
            uint32_t aH[2][4], aL[2][4], bH[4][2], bL[4][2];
#pragma unroll
            for (int mi = 0; mi < 2; mi++) {
                int r = m0 + mi * 16 + g;
                aH[mi][0] = *(const uint32_t*)&sAH[r * 40 + kb + 2 * tg];
                aH[mi][1] = *(const uint32_t*)&sAH[(r + 8) * 40 + kb + 2 * tg];
                aH[mi][2] = *(const uint32_t*)&sAH[r * 40 + kb + 2 * tg + 8];
                aH[mi][3] = *(const uint32_t*)&sAH[(r + 8) * 40 + kb + 2 * tg + 8];
                aL[mi][0] = *(const uint32_t*)&sAL[r * 40 + kb + 2 * tg];
                aL[mi][1] = *(const uint32_t*)&sAL[(r + 8) * 40 + kb + 2 * tg];
                aL[mi][2] = *(const uint32_t*)&sAL[r * 40 + kb + 2 * tg + 8];
                aL[mi][3] = *(const uint32_t*)&sAL[(r + 8) * 40 + kb + 2 * tg + 8];
            }
#pragma unroll
            for (int ni = 0; ni < 4; ni++) {
                int r = n0 + ni * 8 + g;
                bH[ni][0] = *(const uint32_t*)&sBH[r * 40 + kb + 2 * tg];
                bH[ni][1] = *(const uint32_t*)&sBH[r * 40 + kb + 2 * tg + 8];
                bL[ni][0] = *(const uint32_t*)&sBL[r * 40 + kb + 2 * tg];
                bL[ni][1] = *(const uint32_t*)&sBL[r * 40 + kb + 2 * tg + 8];
            }
#pragma unroll
            for (int mi = 0; mi < 2; mi++)
#pragma unroll
                for (int ni = 0; ni < 4; ni++) {
                    mma16816(d[mi][ni], aH[mi], bH[ni]);
                    mma16816(d[mi][ni], aL[mi], bH[ni]);
                    mma16816(d[mi][ni], aH[mi], bL[ni]);
                }
        }
        __syncthreads();
    }

#pragma unroll
    for (int mi = 0; mi < 2; mi++) {
#pragma unroll
        for (int rr = 0; rr < 2; rr++) {
            int r = row0 + m0 + mi * 16 + g + rr * 8;
            if (r >= M) continue;
            size_t rowbase;
            if (remapT > 0) {
                int bb = r / remapT, tt = r - bb * remapT;
                rowbase = ((size_t)bb * (remapT + 1) + tt + 1) * (size_t)ldC;
            } else {
                rowbase = (size_t)r * ldC;
            }
#pragma unroll
            for (int ni = 0; ni < 4; ni++) {
#pragma unroll
                for (int cc = 0; cc < 2; cc++) {
                    int col = col0 + n0 + ni * 8 + 2 * tg + cc;
                    if (col >= Nreal) continue;
                    float v = d[mi][ni][rr * 2 + cc]
                            + (b1 ? __ldg(b1 + col) : 0.f) + (b2 ? __ldg(b2 + col) : 0.f);
                    if (relu) v = fmaxf(v, 0.f);
                    if (Cf) Cf[rowbase + col] = v;
                    if (CH) {
                        __nv_bfloat16 hi, lo; bf16_split(v, hi, lo);
                        CH[rowbase + col] = hi;
                        CL[rowbase + col] = lo;
                    }
                }
            }
        }
    }
}

// ---------------- persistent LSTM scan (HMMA, reg-resident weights) --------
// Grid: 128 CTAs = 4 batch-groups(16 batches) x 32 hidden-tiles(16 hidden).
// Weights split to bf16 hi/lo in smem once, then all B fragments hoisted into
// registers (rbH/rbL, 128 regs) -> zero weight LDS in the t-loop.
// h published as packed (hi,lo) bf16 pairs (uint32) -> consumers de-interleave
// with PRMT, no per-step float->bf16 conversion. Barrier: proven atomicAdd.
#define SW_K     520
#define SOFF_WL  (64 * SW_K)               // 33280
#define SOFF_HH  (2 * 64 * SW_K)           // 66560
#define SOFF_HL  (SOFF_HH + 16 * SW_K)     // 74880
#define SCAN_BF16_ELEMS (SOFF_HL + 16 * SW_K)   // 83200
#define SCAN_RED_FLOATS (8 * 16 * 66)      // 8448
#define SCAN_SMEM_BYTES (SCAN_BF16_ELEMS * 2 + SCAN_RED_FLOATS * 4)  // 200192

__device__ __forceinline__ float sigf(float x) { return 1.f / (1.f + expf(-x)); }

__device__ __forceinline__ void group_barrier(unsigned* bar, int bg, unsigned target) {
    __threadfence();
    __syncthreads();
    if (threadIdx.x == 0) {
        atomicAdd(&bar[bg], 1u);
        while (atomicAdd(&bar[bg], 0u) < target) { }
        __threadfence();
    }
    __syncthreads();
}

__global__ void __launch_bounds__(256, 1)
lstm_scan_kernel(const float* __restrict__ gx, const float* __restrict__ Whh,
                 const float* __restrict__ h0, const float* __restrict__ c0,
                 __nv_bfloat16* __restrict__ hsH, __nv_bfloat16* __restrict__ hsL,
                 float* __restrict__ hT_out, float* __restrict__ cT_out,
                 float* __restrict__ hpub, unsigned* __restrict__ bar, int T) {
    extern __shared__ __align__(16) __nv_bfloat16 sm[];
    __nv_bfloat16* sWH = sm;                 // [64][520] (used once)
    __nv_bfloat16* sWL = sm + SOFF_WL;       // [64][520] (used once)
    __nv_bfloat16* sHH = sm + SOFF_HH;       // [16][520]
    __nv_bfloat16* sHL = sm + SOFF_HL;       // [16][520]
    float* red = (float*)(sm + SCAN_BF16_ELEMS);  // [8][16][66]

    uint32_t* hpub32 = (uint32_t*)hpub;      // packed (hi | lo<<16) bf16 pairs

    const int tid = threadIdx.x;
    const int bg = blockIdx.x >> 5;
    const int ht = blockIdx.x & 31;
    const int B0 = bg * 16;
    const int J0 = ht * 16;
    const int w = tid >> 5;
    const int lane = tid & 31;
    const int g = lane >> 2, tg = lane & 3;

    // ---- load + split Whh slice into smem (once); n = gate*16 + j ----
    for (int idx = tid; idx < 64 * 512; idx += 256) {
        int n = idx >> 9, k = idx & 511;
        float v = Whh[(size_t)((n >> 4) * 512 + J0 + (n & 15)) * 512 + k];
        __nv_bfloat16 hi, lo; bf16_split(v, hi, lo);
        sWH[n * SW_K + k] = hi;
        sWL[n * SW_K + k] = lo;
    }

    // ---- init states ----
    const int ub = tid >> 4;            // batch within tile (0..15)
    const int uj = tid & 15;            // hidden within tile (0..15)
    float cval = c0 ? c0[(B0 + ub) * 512 + J0 + uj] : 0.f;
    float hval = h0 ? h0[(B0 + ub) * 512 + J0 + uj] : 0.f;
    {
        __nv_bfloat16 hi, lo; bf16_split(hval, hi, lo);
        uint32_t hp = (uint32_t)__bfloat16_as_ushort(hi)
                    | ((uint32_t)__bfloat16_as_ushort(lo) << 16);
        hpub32[32768 + (B0 + ub) * 512 + J0 + uj] = hp;   // parity-1 feeds t=0
    }

    unsigned nbar = 1;
    group_barrier(bar, bg, nbar * 32);   // covers weight-fill visibility too

    // ---- hoist B (weight) fragments into registers: [ks][ni][2] ----
    uint32_t rbH[4][8][2], rbL[4][8][2];
#pragma unroll
    for (int ks = 0; ks < 4; ks++) {
        const int kb = w * 64 + ks * 16;
#pragma unroll
        for (int ni = 0; ni < 8; ni++) {
            int r = ni * 8 + g;
            rbH[ks][ni][0] = *(const uint32_t*)&sWH[r * SW_K + kb + 2 * tg];
            rbH[ks][ni][1] = *(const uint32_t*)&sWH[r * SW_K + kb + 2 * tg + 8];
            rbL[ks][ni][0] = *(const uint32_t*)&sWL[r * SW_K + kb + 2 * tg];
            rbL[ks][ni][1] = *(const uint32_t*)&sWL[r * SW_K + kb + 2 * tg + 8];
        }
    }

    const int p1b = tid & 15;
    const int p1k = tid >> 4;

    const float* gxrow = gx + ((size_t)(B0 + ub) * T) * G4 + J0 + uj;
    __nv_bfloat16* hH = hsH ? hsH + ((size_t)(B0 + ub) * T) * 512 + J0 + uj : nullptr;
    __nv_bfloat16* hL = hsL ? hsL + ((size_t)(B0 + ub) * T) * 512 + J0 + uj : nullptr;

    for (int t = 0; t < T; ++t) {
        float pgi = gxrow[0], pgf = gxrow[512], pgg = gxrow[1024], pgo = gxrow[1536];

        const uint32_t* hsrc = hpub32 + (((t + 1) & 1) << 15);

        // phase 1: load packed h pairs, de-interleave hi/lo via PRMT
#pragma unroll
        for (int i = 0; i < 8; ++i) {
            int kq = p1k + (i << 4);                  // uint4 index 0..127
            uint4 hv = __ldcg((const uint4*)(hsrc + (B0 + p1b) * 512 + (kq << 2)));
            int base = p1b * SW_K + (kq << 2);
            *(uint32_t*)&sHH[base]     = __byte_perm(hv.x, hv.y, 0x5410);
            *(uint32_t*)&sHL[base]     = __byte_perm(hv.x, hv.y, 0x7632);
            *(uint32_t*)&sHH[base + 2] = __byte_perm(hv.z, hv.w, 0x5410);
            *(uint32_t*)&sHL[base + 2] = __byte_perm(hv.z, hv.w, 0x7632);
        }
        __syncthreads();

        // phase 2: HMMA m16 x n64 x k64, weights from registers
        float c[8][4];
#pragma unroll
        for (int ni = 0; ni < 8; ni++)
#pragma unroll
            for (int q = 0; q < 4; q++) c[ni][q] = 0.f;

        const int kb0 = w * 64;
#pragma unroll
        for (int ks = 0; ks < 4; ks++) {
            const int kb = kb0 + ks * 16;
            uint32_t aH[4], aL[4];
            aH[0] = *(const uint32_t*)&sHH[g * SW_K + kb + 2 * tg];
            aH[1] = *(const uint32_t*)&sHH[(g + 8) * SW_K + kb + 2 * tg];
            aH[2] = *(const uint32_t*)&sHH[g * SW_K + kb + 2 * tg + 8];
            aH[3] = *(const uint32_t*)&sHH[(g + 8) * SW_K + kb + 2 * tg + 8];
            aL[0] = *(const uint32_t*)&sHL[g * SW_K + kb + 2 * tg];
            aL[1] = *(const uint32_t*)&sHL[(g + 8) * SW_K + kb + 2 * tg];
            aL[2] = *(const uint32_t*)&sHL[g * SW_K + kb + 2 * tg + 8];
            aL[3] = *(const uint32_t*)&sHL[(g + 8) * SW_K + kb + 2 * tg + 8];
#pragma unroll
            for (int ni = 0; ni < 8; ni++) {
                mma16816(c[ni], aH, rbH[ks][ni]);
                mma16816(c[ni], aL, rbH[ks][ni]);
                mma16816(c[ni], aH, rbL[ks][ni]);
            }
        }

        // phase 3: fragments -> red[w][m][n] (pad 66)
#pragma unroll
        for (int ni = 0; ni < 8; ni++) {
            int nn = ni * 8 + 2 * tg;
            float2 v01 = make_float2(c[ni][0], c[ni][1]);
            float2 v23 = make_float2(c[ni][2], c[ni][3]);
            *(float2*)&red[w * 1056 + g * 66 + nn] = v01;
            *(float2*)&red[w * 1056 + (g + 8) * 66 + nn] = v23;
        }
        __syncthreads();

        // phase 4: reduce 8 k-slices, add gx, LSTM cell (thread = (ub,uj))
        float gsum[4];
#pragma unroll
        for (int gt = 0; gt < 4; gt++) {
            float v = 0.f;
#pragma unroll
            for (int s2 = 0; s2 < 8; s2++)
                v += red[s2 * 1056 + ub * 66 + gt * 16 + uj];
            gsum[gt] = v;
        }
        float gi = gsum[0] + pgi, gf = gsum[1] + pgf;
        float gg = gsum[2] + pgg, go = gsum[3] + pgo;

        float ig = sigf(gi), fg = sigf(gf), og_ = sigf(go), gt_ = tanhf(gg);
        cval = fg * cval + ig * gt_;
        hval = og_ * tanhf(cval);

        __nv_bfloat16 hi, lo; bf16_split(hval, hi, lo);
        uint32_t hp = (uint32_t)__bfloat16_as_ushort(hi)
                    | ((uint32_t)__bfloat16_as_ushort(lo) << 16);
        hpub32[((t & 1) << 15) + (B0 + ub) * 512 + J0 + uj] = hp;
        if (hH) { *hH = hi; *hL = lo; hH += 512; hL += 512; }
        gxrow += G4;

        ++nbar;
        group_barrier(bar, bg, nbar * 32);
    }

    hT_out[(B0 + ub) * 512 + J0 + uj] = hval;
    cT_out[(B0 + ub) * 512 + J0 + uj] = cval;
}

// ---------------- host orchestration ----------------
static __nv_bfloat16 *s_AH, *s_AL, *s_MH, *s_ML, *s_WH, *s_WL;

static void launch_mma(const __nv_bfloat16* AH, const __nv_bfloat16* AL,
                       int kpad, const float* b1, const float* b2,
                       float* Cf, __nv_bfloat16* CH, __nv_bfloat16* CL,
                       int ldC, int M, int Nreal, int relu, int remapT) {
    int mt = (M + 127) / 128;
    int nt = (Nreal + 63) / 64;
    int nChunks = kpad / 32;
    mma_gemm_kernel<<<dim3(nt, mt), 256, MMA_SMEM_BYTES>>>(
        AH, AL, s_WH, s_WL, kpad, nChunks, b1, b2, Cf, CH, CL, ldC, M, Nreal, relu, remapT);
}

static void launch_convw(const float* W, int N, int K, int kpad) {
    int Npad = ((N + 63) / 64) * 64;
    long n = (long)Npad * kpad;
    conv_w_kernel<<<(int)((n + 255) / 256), 256>>>(W, s_WH, s_WL, N, K, kpad, Npad);
}

extern "C" void kernel_launch(void* const* d_in, const int* in_sizes, int n_in,
                              void* d_out, int out_size) {
    (void)in_sizes; (void)n_in; (void)out_size;
    const float* x     = (const float*)d_in[0];
    const float* y     = (const float*)d_in[1];
    const float* eWih0 = (const float*)d_in[2];
    const float* eWhh0 = (const float*)d_in[3];
    const float* ebih0 = (const float*)d_in[4];
    const float* ebhh0 = (const float*)d_in[5];
    const float* eWih1 = (const float*)d_in[6];
    const float* eWhh1 = (const float*)d_in[7];
    const float* ebih1 = (const float*)d_in[8];
    const float* ebhh1 = (const float*)d_in[9];
    const float* dWih0 = (const float*)d_in[10];
    const float* dWhh0 = (const float*)d_in[11];
    const float* dbih0 = (const float*)d_in[12];
    const float* dbhh0 = (const float*)d_in[13];
    const float* dWih1 = (const float*)d_in[14];
    const float* dWhh1 = (const float*)d_in[15];
    const float* dbih1 = (const float*)d_in[16];
    const float* dbhh1 = (const float*)d_in[17];
    const float* clsW1 = (const float*)d_in[18];
    const float* clsb1 = (const float*)d_in[19];
    const float* clsW2 = (const float*)d_in[20];
    const float* clsb2 = (const float*)d_in[21];
    float* out = (float*)d_out;

    float *gx, *hpub, *hT0, *cT0, *hT1, *cT1, *hTd, *cTd;
    unsigned* bar;
    cudaGetSymbolAddress((void**)&gx,   g_gx);
    cudaGetSymbolAddress((void**)&hpub, g_hpub);
    cudaGetSymbolAddress((void**)&hT0,  g_hT0);
    cudaGetSymbolAddress((void**)&cT0,  g_cT0);
    cudaGetSymbolAddress((void**)&hT1,  g_hT1);
    cudaGetSymbolAddress((void**)&cT1,  g_cT1);
    cudaGetSymbolAddress((void**)&hTd,  g_hTd);
    cudaGetSymbolAddress((void**)&cTd,  g_cTd);
    cudaGetSymbolAddress((void**)&bar,  g_bar);
    cudaGetSymbolAddress((void**)&s_AH, g_AH);
    cudaGetSymbolAddress((void**)&s_AL, g_AL);
    cudaGetSymbolAddress((void**)&s_MH, g_MH);
    cudaGetSymbolAddress((void**)&s_ML, g_ML);
    cudaGetSymbolAddress((void**)&s_WH, g_WHb);
    cudaGetSymbolAddress((void**)&s_WL, g_WLb);

    cudaFuncSetAttribute(lstm_scan_kernel,
                         cudaFuncAttributeMaxDynamicSharedMemorySize, SCAN_SMEM_BYTES);
    cudaFuncSetAttribute(mma_gemm_kernel,
                         cudaFuncAttributeMaxDynamicSharedMemorySize, MMA_SMEM_BYTES);

    const int ME  = MROWS_MAX;   // 65600
    const int MDN = MD_ROWS;     // 65472

    // ---------------- encoder ----------------
    {
        long n = (long)BATCH * T_ENC * 192;
        pad_shift_bf16_kernel<<<(int)((n + 255) / 256), 256>>>(x, s_AH, s_AL, 1024, T_ENC, 1024);
    }
    launch_convw(eWih0, G4, DIN, 192);
    launch_mma(s_AH, s_AL, 192, ebih0, ebhh0, gx, nullptr, nullptr, G4, ME, G4, 0, 0);
    reset_bar_kernel<<<1, 32>>>(bar);
    lstm_scan_kernel<<<128, 256, SCAN_SMEM_BYTES>>>(gx, eWhh0, nullptr, nullptr,
                                                    s_AH, s_AL, hT0, cT0, hpub, bar, T_ENC);
    launch_convw(eWih1, G4, HID, 512);
    launch_mma(s_AH, s_AL, 512, ebih1, ebhh1, gx, nullptr, nullptr, G4, ME, G4, 0, 0);
    reset_bar_kernel<<<1, 32>>>(bar);
    lstm_scan_kernel<<<128, 256, SCAN_SMEM_BYTES>>>(gx, eWhh1, nullptr, nullptr,
                                                    nullptr, nullptr, hT1, cT1, hpub, bar, T_ENC);

    // ---------------- decoder ----------------
    {
        long n = (long)BATCH * T_DEC * 192;
        pad_shift_bf16_kernel<<<(int)((n + 255) / 256), 256>>>(y, s_AH, s_AL, 1024, T_DEC, 1022);
    }
    launch_convw(dWih0, G4, DIN, 192);
    launch_mma(s_AH, s_AL, 192, dbih0, dbhh0, gx, nullptr, nullptr, G4, MDN, G4, 0, 0);
    reset_bar_kernel<<<1, 32>>>(bar);
    lstm_scan_kernel<<<128, 256, SCAN_SMEM_BYTES>>>(gx, dWhh0, hT0, cT0,
                                                    s_AH, s_AL, hTd, cTd, hpub, bar, T_DEC);
    launch_convw(dWih1, G4, HID, 512);
    launch_mma(s_AH, s_AL, 512, dbih1, dbhh1, gx, nullptr, nullptr, G4, MDN, G4, 0, 0);
    reset_bar_kernel<<<1, 32>>>(bar);
    lstm_scan_kernel<<<128, 256, SCAN_SMEM_BYTES>>>(gx, dWhh1, hT1, cT1,
                                                    s_AH, s_AL, hTd, cTd, hpub, bar, T_DEC);

    // ---------------- classifier ----------------
    launch_convw(clsW1, 256, HID, 512);
    launch_mma(s_AH, s_AL, 512, clsb1, nullptr, nullptr, s_MH, s_ML, 256, MDN, 256, 1, 0);
    launch_convw(clsW2, DIN, 256, 256);
    launch_mma(s_MH, s_ML, 256, clsb2, nullptr, out, nullptr, nullptr, DIN, MDN, DIN, 0, T_DEC);
    zero_t0_kernel<<<(BATCH * DIN + 255) / 256, 256>>>(out);
}

// round 12
// speedup vs baseline: 1.0136x; 1.0136x over previous
#include <cuda_runtime.h>
#include <cuda_bf16.h>
#include <cstdint>

typedef unsigned long long ull;

// ---------------- problem constants ----------------
#define BATCH 64
#define DIN   176
#define HID   512
#define G4    2048          // 4*HID
#define T_ENC 1025          // 1 + 1024
#define T_DEC 1023          // TTGT - 1
#define MROWS_MAX (BATCH * T_ENC)   // 65600
#define MD_ROWS   (BATCH * T_DEC)   // 65472

// ---------------- scratch (static device globals; no cudaMalloc allowed) ----
__device__ float g_gx[(size_t)MROWS_MAX * G4];     // per-layer gx (fp32)
#define ABUF_ROWS (MROWS_MAX + 128)
__device__ __nv_bfloat16 g_AH[(size_t)ABUF_ROWS * 512];   // A operand hi
__device__ __nv_bfloat16 g_AL[(size_t)ABUF_ROWS * 512];   // A operand lo
#define MBUF_ROWS (MD_ROWS + 128)
__device__ __nv_bfloat16 g_MH[(size_t)MBUF_ROWS * 256];   // hmid hi
__device__ __nv_bfloat16 g_ML[(size_t)MBUF_ROWS * 256];   // hmid lo
__device__ __nv_bfloat16 g_WHb[2048 * 512];               // W operand hi
__device__ __nv_bfloat16 g_WLb[2048 * 512];               // W operand lo
__device__ float g_hpub[2 * BATCH * HID];                 // packed (hi,lo) bf16 pairs
__device__ float g_hT0[BATCH * HID], g_cT0[BATCH * HID];
__device__ float g_hT1[BATCH * HID], g_cT1[BATCH * HID];
__device__ float g_hTd[BATCH * HID], g_cTd[BATCH * HID];
__device__ unsigned g_bar[4];

// ---------------- helpers ----------------
__device__ __forceinline__ void bf16_split(float v, __nv_bfloat16& hi, __nv_bfloat16& lo) {
    hi = __float2bfloat16(v);
    lo = __float2bfloat16(v - __bfloat162float(hi));
}

__device__ __forceinline__ uint32_t smem_to_u32(const void* p) {
    uint32_t a;
    asm("{ .reg .u64 t; cvta.to.shared.u64 t, %1; cvt.u32.u64 %0, t; }" : "=r"(a) : "l"(p));
    return a;
}

// HMMA m16n8k16 bf16 (non-arch-gated PTX; runs on sm_103 base target)
__device__ __forceinline__ void mma16816(float* d, const uint32_t* a, const uint32_t* b) {
    asm volatile(
        "mma.sync.aligned.m16n8k16.row.col.f32.bf16.bf16.f32 "
        "{%0,%1,%2,%3}, {%4,%5,%6,%7}, {%8,%9}, {%0,%1,%2,%3};"
        : "+f"(d[0]), "+f"(d[1]), "+f"(d[2]), "+f"(d[3])
        : "r"(a[0]), "r"(a[1]), "r"(a[2]), "r"(a[3]), "r"(b[0]), "r"(b[1]));
}

// cp.async 16B (LDGSTS; sm_80 PTX, non-gated)
__device__ __forceinline__ void cpasync16(uint32_t s, const void* g) {
    asm volatile("cp.async.cg.shared.global [%0], [%1], 16;" :: "r"(s), "l"(g));
}
#define CP_COMMIT() asm volatile("cp.async.commit_group;" ::: "memory")
#define CP_WAIT1()  asm volatile("cp.async.wait_group 1;" ::: "memory")

// ---------------- small utility kernels ----------------
__global__ void reset_bar_kernel(unsigned* bar) {
    if (threadIdx.x < 4) bar[threadIdx.x] = 0u;
}

// padded-shifted input -> bf16 hi/lo, layout [b][t][192] (cols 176..191 zero)
__global__ void pad_shift_bf16_kernel(const float* __restrict__ src,
                                      __nv_bfloat16* __restrict__ dH,
                                      __nv_bfloat16* __restrict__ dL,
                                      int Tsrc, int Tpad, int Tcopy) {
    long n = (long)BATCH * Tpad * 192;
    long i = (long)blockIdx.x * blockDim.x + threadIdx.x;
    if (i >= n) return;
    int d = (int)(i % 192);
    long bt = i / 192;
    int t = (int)(bt % Tpad);
    int b = (int)(bt / Tpad);
    float v = (d < DIN && t > 0 && t <= Tcopy) ? src[((long)b * Tsrc + (t - 1)) * DIN + d] : 0.f;
    __nv_bfloat16 hi, lo; bf16_split(v, hi, lo);
    dH[i] = hi; dL[i] = lo;
}

// W (N x K fp32) -> WH/WL (Npad x kpad bf16, zero padded)
__global__ void conv_w_kernel(const float* __restrict__ W,
                              __nv_bfloat16* __restrict__ WH, __nv_bfloat16* __restrict__ WL,
                              int N, int K, int kpad, int Npad) {
    long n = (long)Npad * kpad;
    long i = (long)blockIdx.x * blockDim.x + threadIdx.x;
    if (i >= n) return;
    int row = (int)(i / kpad), c = (int)(i % kpad);
    float v = (row < N && c < K) ? W[(size_t)row * K + c] : 0.f;
    __nv_bfloat16 hi, lo; bf16_split(v, hi, lo);
    WH[i] = hi; WL[i] = lo;
}

__global__ void zero_t0_kernel(float* __restrict__ out) {
    int i = blockIdx.x * blockDim.x + threadIdx.x;
    if (i < BATCH * DIN) {
        int b = i / DIN, d = i % DIN;
        out[(size_t)b * 1024 * DIN + d] = 0.f;
    }
}

// ---------------- HMMA GEMM (128x128 tile, cp.async 2-stage) ---------------
// C(MxN) = A(MxK) * W(NxK)^T + b1 + b2 via bf16 2-way split (3 mma terms).
// CTA = 128x128 tile, 256 threads = 8 warps (4m x 2n), warp tile 32x64.
// K in chunks of 32; double-buffered smem filled by cp.async.
// Stage layout (bf16 elems): AH[128*40] AL BH[128*40] BL
#define SOFF_AL  5120
#define SOFF_BH  10240
#define SOFF_BL  15360
#define STG_ELEMS 20480
#define MMA_SMEM_BYTES (2 * STG_ELEMS * 2)   // 81920

__global__ void __launch_bounds__(256, 2)
mma_gemm_kernel(const __nv_bfloat16* __restrict__ AH, const __nv_bfloat16* __restrict__ AL,
                const __nv_bfloat16* __restrict__ WH, const __nv_bfloat16* __restrict__ WL,
                int kpad, int nChunks,
                const float* __restrict__ b1, const float* __restrict__ b2,
                float* __restrict__ Cf, __nv_bfloat16* __restrict__ CH,
                __nv_bfloat16* __restrict__ CL,
                int ldC, int M, int Nreal, int relu, int remapT) {
    extern __shared__ __align__(16) __nv_bfloat16 smbuf[];
    const uint32_t sb = smem_to_u32(smbuf);

    const int tid  = threadIdx.x;
    const int wid  = tid >> 5, lane = tid & 31;
    const int g    = lane >> 2, tg = lane & 3;
    const int m0   = (wid & 3) * 32;
    const int n0   = (wid >> 2) * 64;
    const int row0 = blockIdx.y * 128;
    const int col0 = blockIdx.x * 128;

    const int lr0 = tid >> 2, lseg = tid & 3;   // loader: rows lr0, lr0+64

    float d[2][8][4];
#pragma unroll
    for (int mi = 0; mi < 2; mi++)
#pragma unroll
        for (int ni = 0; ni < 8; ni++)
#pragma unroll
            for (int q = 0; q < 4; q++) d[mi][ni][q] = 0.f;

    auto load_chunk = [&](int ch, int stg) {
        const int kbase = ch * 32;
        const uint32_t base = sb + stg * (STG_ELEMS * 2);
#pragma unroll
        for (int i = 0; i < 2; i++) {
            int r = lr0 + i * 64;
            size_t ga = (size_t)(row0 + r) * kpad + kbase + lseg * 8;
            size_t gb = (size_t)(col0 + r) * kpad + kbase + lseg * 8;
            uint32_t so = base + (r * 40 + lseg * 8) * 2;
            cpasync16(so, AH + ga);
            cpasync16(so + SOFF_AL * 2, AL + ga);
            cpasync16(so + SOFF_BH * 2, WH + gb);
            cpasync16(so + SOFF_BL * 2, WL + gb);
        }
    };

    load_chunk(0, 0);
    CP_COMMIT();

    for (int ch = 0; ch < nChunks; ch++) {
        const int cur = ch & 1;
        if (ch + 1 < nChunks) load_chunk(ch + 1, cur ^ 1);
        CP_COMMIT();
        CP_WAIT1();
        __syncthreads();

        const __nv_bfloat16* sAH = smbuf + cur * STG_ELEMS;
        const __nv_bfloat16* sAL = sAH + SOFF_AL;
        const __nv_bfloat16* sBH = smbuf + cur * STG_ELEMS + SOFF_BH;
        const __nv_bfloat16* sBL = smbuf + cur * STG_ELEMS + SOFF_BL;

#pragma unroll
        for (int ks = 0; ks < 2; ks++) {
            const int kb = ks * 16;
            uint32_t aH[2][4], aL[2][4];
#pragma unroll
            for (int mi = 0; mi < 2; mi++) {
                int r = m0 + mi * 16 + g;
                aH[mi][0] = *(const uint32_t*)&sAH[r * 40 + kb + 2 * tg];
                aH[mi][1] = *(const uint32_t*)&sAH[(r + 8) * 40 + kb + 2 * tg];
                aH[mi][2] = *(const uint32_t*)&sAH[r * 40 + kb + 2 * tg + 8];
                aH[mi][3] = *(const uint32_t*)&sAH[(r + 8) * 40 + kb + 2 * tg + 8];
                aL[mi][0] = *(const uint32_t*)&sAL[r * 40 + kb + 2 * tg];
                aL[mi][1] = *(const uint32_t*)&sAL[(r + 8) * 40 + kb + 2 * tg];
                aL[mi][2] = *(const uint32_t*)&sAL[r * 40 + kb + 2 * tg + 8];
                aL[mi][3] = *(const uint32_t*)&sAL[(r + 8) * 40 + kb + 2 * tg + 8];
            }
#pragma unroll
            for (int ni = 0; ni < 8; ni++) {
                int r = n0 + ni * 8 + g;
                uint32_t bH[2], bL[2];
                bH[0] = *(const uint32_t*)&sBH[r * 40 + kb + 2 * tg];
                bH[1] = *(const uint32_t*)&sBH[r * 40 + kb + 2 * tg + 8];
                bL[0] = *(const uint32_t*)&sBL[r * 40 + kb + 2 * tg];
                bL[1] = *(const uint32_t*)&sBL[r * 40 + kb + 2 * tg + 8];
#pragma unroll
                for (int mi = 0; mi < 2; mi++) {
                    mma16816(d[mi][ni], aH[mi], bH);
                    mma16816(d[mi][ni], aL[mi], bH);
                    mma16816(d[mi][ni], aH[mi], bL);
                }
            }
        }
        __syncthreads();
    }

    // epilogue: bias/relu, optional remap, fp32 and/or bf16 hi/lo stores
#pragma unroll
    for (int mi = 0; mi < 2; mi++) {
#pragma unroll
        for (int rr = 0; rr < 2; rr++) {
            int r = row0 + m0 + mi * 16 + g + rr * 8;
            if (r >= M) continue;
            size_t rowbase;
            if (remapT > 0) {
                int bb = r / remapT, tt = r - bb * remapT;
                rowbase = ((size_t)bb * (remapT + 1) + tt + 1) * (size_t)ldC;
            } else {
                rowbase = (size_t)r * ldC;
            }
#pragma unroll
            for (int ni = 0; ni < 8; ni++) {
#pragma unroll
                for (int cc = 0; cc < 2; cc++) {
                    int col = col0 + n0 + ni * 8 + 2 * tg + cc;
                    if (col >= Nreal) continue;
                    float v = d[mi][ni][rr * 2 + cc]
                            + (b1 ? __ldg(b1 + col) : 0.f) + (b2 ? __ldg(b2 + col) : 0.f);
                    if (relu) v = fmaxf(v, 0.f);
                    if (Cf) Cf[rowbase + col] = v;
                    if (CH) {
                        __nv_bfloat16 hi, lo; bf16_split(v, hi, lo);
                        CH[rowbase + col] = hi;
                        CL[rowbase + col] = lo;
                    }
                }
            }
        }
    }
}

// ---------------- persistent LSTM scan (round-11, unchanged) ---------------
#define SW_K     520
#define SOFF_WL2 (64 * SW_K)               // 33280
#define SOFF_HH  (2 * 64 * SW_K)           // 66560
#define SOFF_HL  (SOFF_HH + 16 * SW_K)     // 74880
#define SCAN_BF16_ELEMS (SOFF_HL + 16 * SW_K)   // 83200
#define SCAN_RED_FLOATS (8 * 16 * 66)      // 8448
#define SCAN_SMEM_BYTES (SCAN_BF16_ELEMS * 2 + SCAN_RED_FLOATS * 4)  // 200192

__device__ __forceinline__ float sigf(float x) { return 1.f / (1.f + expf(-x)); }

__device__ __forceinline__ void group_barrier(unsigned* bar, int bg, unsigned target) {
    __threadfence();
    __syncthreads();
    if (threadIdx.x == 0) {
        atomicAdd(&bar[bg], 1u);
        while (atomicAdd(&bar[bg], 0u) < target) { }
        __threadfence();
    }
    __syncthreads();
}

__global__ void __launch_bounds__(256, 1)
lstm_scan_kernel(const float* __restrict__ gx, const float* __restrict__ Whh,
                 const float* __restrict__ h0, const float* __restrict__ c0,
                 __nv_bfloat16* __restrict__ hsH, __nv_bfloat16* __restrict__ hsL,
                 float* __restrict__ hT_out, float* __restrict__ cT_out,
                 float* __restrict__ hpub, unsigned* __restrict__ bar, int T) {
    extern __shared__ __align__(16) __nv_bfloat16 sm[];
    __nv_bfloat16* sWH = sm;                 // [64][520] (used once)
    __nv_bfloat16* sWL = sm + SOFF_WL2;      // [64][520] (used once)
    __nv_bfloat16* sHH = sm + SOFF_HH;       // [16][520]
    __nv_bfloat16* sHL = sm + SOFF_HL;       // [16][520]
    float* red = (float*)(sm + SCAN_BF16_ELEMS);  // [8][16][66]

    uint32_t* hpub32 = (uint32_t*)hpub;      // packed (hi | lo<<16) bf16 pairs

    const int tid = threadIdx.x;
    const int bg = blockIdx.x >> 5;
    const int ht = blockIdx.x & 31;
    const int B0 = bg * 16;
    const int J0 = ht * 16;
    const int w = tid >> 5;
    const int lane = tid & 31;
    const int g = lane >> 2, tg = lane & 3;

    // ---- load + split Whh slice into smem (once); n = gate*16 + j ----
    for (int idx = tid; idx < 64 * 512; idx += 256) {
        int n = idx >> 9, k = idx & 511;
        float v = Whh[(size_t)((n >> 4) * 512 + J0 + (n & 15)) * 512 + k];
        __nv_bfloat16 hi, lo; bf16_split(v, hi, lo);
        sWH[n * SW_K + k] = hi;
        sWL[n * SW_K + k] = lo;
    }

    // ---- init states ----
    const int ub = tid >> 4;            // batch within tile (0..15)
    const int uj = tid & 15;            // hidden within tile (0..15)
    float cval = c0 ? c0[(B0 + ub) * 512 + J0 + uj] : 0.f;
    float hval = h0 ? h0[(B0 + ub) * 512 + J0 + uj] : 0.f;
    {
        __nv_bfloat16 hi, lo; bf16_split(hval, hi, lo);
        uint32_t hp = (uint32_t)__bfloat16_as_ushort(hi)
                    | ((uint32_t)__bfloat16_as_ushort(lo) << 16);
        hpub32[32768 + (B0 + ub) * 512 + J0 + uj] = hp;   // parity-1 feeds t=0
    }

    unsigned nbar = 1;
    group_barrier(bar, bg, nbar * 32);   // covers weight-fill visibility too

    // ---- hoist B (weight) fragments into registers: [ks][ni][2] ----
    uint32_t rbH[4][8][2], rbL[4][8][2];
#pragma unroll
    for (int ks = 0; ks < 4; ks++) {
        const int kb = w * 64 + ks * 16;
#pragma unroll
        for (int ni = 0; ni < 8; ni++) {
            int r = ni * 8 + g;
            rbH[ks][ni][0] = *(const uint32_t*)&sWH[r * SW_K + kb + 2 * tg];
            rbH[ks][ni][1] = *(const uint32_t*)&sWH[r * SW_K + kb + 2 * tg + 8];
            rbL[ks][ni][0] = *(const uint32_t*)&sWL[r * SW_K + kb + 2 * tg];
            rbL[ks][ni][1] = *(const uint32_t*)&sWL[r * SW_K + kb + 2 * tg + 8];
        }
    }

    const int p1b = tid & 15;
    const int p1k = tid >> 4;

    const float* gxrow = gx + ((size_t)(B0 + ub) * T) * G4 + J0 + uj;
    __nv_bfloat16* hH = hsH ? hsH + ((size_t)(B0 + ub) * T) * 512 + J0 + uj : nullptr;
    __nv_bfloat16* hL = hsL ? hsL + ((size_t)(B0 + ub) * T) * 512 + J0 + uj : nullptr;

    for (int t = 0; t < T; ++t) {
        float pgi = gxrow[0], pgf = gxrow[512], pgg = gxrow[1024], pgo = gxrow[1536];

        const uint32_t* hsrc = hpub32 + (((t + 1) & 1) << 15);

        // phase 1: load packed h pairs, de-interleave hi/lo via PRMT
#pragma unroll
        for (int i = 0; i < 8; ++i) {
            int kq = p1k + (i << 4);                  // uint4 index 0..127
            uint4 hv = __ldcg((const uint4*)(hsrc + (B0 + p1b) * 512 + (kq << 2)));
            int base = p1b * SW_K + (kq << 2);
            *(uint32_t*)&sHH[base]     = __byte_perm(hv.x, hv.y, 0x5410);
            *(uint32_t*)&sHL[base]     = __byte_perm(hv.x, hv.y, 0x7632);
            *(uint32_t*)&sHH[base + 2] = __byte_perm(hv.z, hv.w, 0x5410);
            *(uint32_t*)&sHL[base + 2] = __byte_perm(hv.z, hv.w, 0x7632);
        }
        __syncthreads();

        // phase 2: HMMA m16 x n64 x k64, weights from registers
        float c[8][4];
#pragma unroll
        for (int ni = 0; ni < 8; ni++)
#pragma unroll
            for (int q = 0; q < 4; q++) c[ni][q] = 0.f;

        const int kb0 = w * 64;
#pragma unroll
        for (int ks = 0; ks < 4; ks++) {
            const int kb = kb0 + ks * 16;
            uint32_t aH[4], aL[4];
            aH[0] = *(const uint32_t*)&sHH[g * SW_K + kb + 2 * tg];
            aH[1] = *(const uint32_t*)&sHH[(g + 8) * SW_K + kb + 2 * tg];
            aH[2] = *(const uint32_t*)&sHH[g * SW_K + kb + 2 * tg + 8];
            aH[3] = *(const uint32_t*)&sHH[(g + 8) * SW_K + kb + 2 * tg + 8];
            aL[0] = *(const uint32_t*)&sHL[g * SW_K + kb + 2 * tg];
            aL[1] = *(const uint32_t*)&sHL[(g + 8) * SW_K + kb + 2 * tg];
            aL[2] = *(const uint32_t*)&sHL[g * SW_K + kb + 2 * tg + 8];
            aL[3] = *(const uint32_t*)&sHL[(g + 8) * SW_K + kb + 2 * tg + 8];
#pragma unroll
            for (int ni = 0; ni < 8; ni++) {
                mma16816(c[ni], aH, rbH[ks][ni]);
                mma16816(c[ni], aL, rbH[ks][ni]);
                mma16816(c[ni], aH, rbL[ks][ni]);
            }
        }

        // phase 3: fragments -> red[w][m][n] (pad 66)
#pragma unroll
        for (int ni = 0; ni < 8; ni++) {
            int nn = ni * 8 + 2 * tg;
            float2 v01 = make_float2(c[ni][0], c[ni][1]);
            float2 v23 = make_float2(c[ni][2], c[ni][3]);
            *(float2*)&red[w * 1056 + g * 66 + nn] = v01;
            *(float2*)&red[w * 1056 + (g + 8) * 66 + nn] = v23;
        }
        __syncthreads();

        // phase 4: reduce 8 k-slices, add gx, LSTM cell (thread = (ub,uj))
        float gsum[4];
#pragma unroll
        for (int gt = 0; gt < 4; gt++) {
            float v = 0.f;
#pragma unroll
            for (int s2 = 0; s2 < 8; s2++)
                v += red[s2 * 1056 + ub * 66 + gt * 16 + uj];
            gsum[gt] = v;
        }
        float gi = gsum[0] + pgi, gf = gsum[1] + pgf;
        float gg = gsum[2] + pgg, go = gsum[3] + pgo;

        float ig = sigf(gi), fg = sigf(gf), og_ = sigf(go), gt_ = tanhf(gg);
        cval = fg * cval + ig * gt_;
        hval = og_ * tanhf(cval);

        __nv_bfloat16 hi, lo; bf16_split(hval, hi, lo);
        uint32_t hp = (uint32_t)__bfloat16_as_ushort(hi)
                    | ((uint32_t)__bfloat16_as_ushort(lo) << 16);
        hpub32[((t & 1) << 15) + (B0 + ub) * 512 + J0 + uj] = hp;
        if (hH) { *hH = hi; *hL = lo; hH += 512; hL += 512; }
        gxrow += G4;

        ++nbar;
        group_barrier(bar, bg, nbar * 32);
    }

    hT_out[(B0 + ub) * 512 + J0 + uj] = hval;
    cT_out[(B0 + ub) * 512 + J0 + uj] = cval;
}

// ---------------- host orchestration ----------------
static __nv_bfloat16 *s_AH, *s_AL, *s_MH, *s_ML, *s_WH, *s_WL;

static void launch_mma(const __nv_bfloat16* AH, const __nv_bfloat16* AL,
                       int kpad, const float* b1, const float* b2,
                       float* Cf, __nv_bfloat16* CH, __nv_bfloat16* CL,
                       int ldC, int M, int Nreal, int relu, int remapT) {
    int mt = (M + 127) / 128;
    int nt = (Nreal + 127) / 128;
    int nChunks = kpad / 32;
    mma_gemm_kernel<<<dim3(nt, mt), 256, MMA_SMEM_BYTES>>>(
        AH, AL, s_WH, s_WL, kpad, nChunks, b1, b2, Cf, CH, CL, ldC, M, Nreal, relu, remapT);
}

static void launch_convw(const float* W, int N, int K, int kpad) {
    int Npad = ((N + 63) / 64) * 64;
    long n = (long)Npad * kpad;
    conv_w_kernel<<<(int)((n + 255) / 256), 256>>>(W, s_WH, s_WL, N, K, kpad, Npad);
}

extern "C" void kernel_launch(void* const* d_in, const int* in_sizes, int n_in,
                              void* d_out, int out_size) {
    (void)in_sizes; (void)n_in; (void)out_size;
    const float* x     = (const float*)d_in[0];
    const float* y     = (const float*)d_in[1];
    const float* eWih0 = (const float*)d_in[2];
    const float* eWhh0 = (const float*)d_in[3];
    const float* ebih0 = (const float*)d_in[4];
    const float* ebhh0 = (const float*)d_in[5];
    const float* eWih1 = (const float*)d_in[6];
    const float* eWhh1 = (const float*)d_in[7];
    const float* ebih1 = (const float*)d_in[8];
    const float* ebhh1 = (const float*)d_in[9];
    const float* dWih0 = (const float*)d_in[10];
    const float* dWhh0 = (const float*)d_in[11];
    const float* dbih0 = (const float*)d_in[12];
    const float* dbhh0 = (const float*)d_in[13];
    const float* dWih1 = (const float*)d_in[14];
    const float* dWhh1 = (const float*)d_in[15];
    const float* dbih1 = (const float*)d_in[16];
    const float* dbhh1 = (const float*)d_in[17];
    const float* clsW1 = (const float*)d_in[18];
    const float* clsb1 = (const float*)d_in[19];
    const float* clsW2 = (const float*)d_in[20];
    const float* clsb2 = (const float*)d_in[21];
    float* out = (float*)d_out;

    float *gx, *hpub, *hT0, *cT0, *hT1, *cT1, *hTd, *cTd;
    unsigned* bar;
    cudaGetSymbolAddress((void**)&gx,   g_gx);
    cudaGetSymbolAddress((void**)&hpub, g_hpub);
    cudaGetSymbolAddress((void**)&hT0,  g_hT0);
    cudaGetSymbolAddress((void**)&cT0,  g_cT0);
    cudaGetSymbolAddress((void**)&hT1,  g_hT1);
    cudaGetSymbolAddress((void**)&cT1,  g_cT1);
    cudaGetSymbolAddress((void**)&hTd,  g_hTd);
    cudaGetSymbolAddress((void**)&cTd,  g_cTd);
    cudaGetSymbolAddress((void**)&bar,  g_bar);
    cudaGetSymbolAddress((void**)&s_AH, g_AH);
    cudaGetSymbolAddress((void**)&s_AL, g_AL);
    cudaGetSymbolAddress((void**)&s_MH, g_MH);
    cudaGetSymbolAddress((void**)&s_ML, g_ML);
    cudaGetSymbolAddress((void**)&s_WH, g_WHb);
    cudaGetSymbolAddress((void**)&s_WL, g_WLb);

    cudaFuncSetAttribute(lstm_scan_kernel,
                         cudaFuncAttributeMaxDynamicSharedMemorySize, SCAN_SMEM_BYTES);
    cudaFuncSetAttribute(mma_gemm_kernel,
                         cudaFuncAttributeMaxDynamicSharedMemorySize, MMA_SMEM_BYTES);

    const int ME  = MROWS_MAX;   // 65600
    const int MDN = MD_ROWS;     // 65472

    // ---------------- encoder ----------------
    {
        long n = (long)BATCH * T_ENC * 192;
        pad_shift_bf16_kernel<<<(int)((n + 255) / 256), 256>>>(x, s_AH, s_AL, 1024, T_ENC, 1024);
    }
    launch_convw(eWih0, G4, DIN, 192);
    launch_mma(s_AH, s_AL, 192, ebih0, ebhh0, gx, nullptr, nullptr, G4, ME, G4, 0, 0);
    reset_bar_kernel<<<1, 32>>>(bar);
    lstm_scan_kernel<<<128, 256, SCAN_SMEM_BYTES>>>(gx, eWhh0, nullptr, nullptr,
                                                    s_AH, s_AL, hT0, cT0, hpub, bar, T_ENC);
    launch_convw(eWih1, G4, HID, 512);
    launch_mma(s_AH, s_AL, 512, ebih1, ebhh1, gx, nullptr, nullptr, G4, ME, G4, 0, 0);
    reset_bar_kernel<<<1, 32>>>(bar);
    lstm_scan_kernel<<<128, 256, SCAN_SMEM_BYTES>>>(gx, eWhh1, nullptr, nullptr,
                                                    nullptr, nullptr, hT1, cT1, hpub, bar, T_ENC);

    // ---------------- decoder ----------------
    {
        long n = (long)BATCH * T_DEC * 192;
        pad_shift_bf16_kernel<<<(int)((n + 255) / 256), 256>>>(y, s_AH, s_AL, 1024, T_DEC, 1022);
    }
    launch_convw(dWih0, G4, DIN, 192);
    launch_mma(s_AH, s_AL, 192, dbih0, dbhh0, gx, nullptr, nullptr, G4, MDN, G4, 0, 0);
    reset_bar_kernel<<<1, 32>>>(bar);
    lstm_scan_kernel<<<128, 256, SCAN_SMEM_BYTES>>>(gx, dWhh0, hT0, cT0,
                                                    s_AH, s_AL, hTd, cTd, hpub, bar, T_DEC);
    launch_convw(dWih1, G4, HID, 512);
    launch_mma(s_AH, s_AL, 512, dbih1, dbhh1, gx, nullptr, nullptr, G4, MDN, G4, 0, 0);
    reset_bar_kernel<<<1, 32>>>(bar);
    lstm_scan_kernel<<<128, 256, SCAN_SMEM_BYTES>>>(gx, dWhh1, hT1, cT1,
                                                    s_AH, s_AL, hTd, cTd, hpub, bar, T_DEC);

    // ---------------- classifier ----------------
    launch_convw(clsW1, 256, HID, 512);
    launch_mma(s_AH, s_AL, 512, clsb1, nullptr, nullptr, s_MH, s_ML, 256, MDN, 256, 1, 0);
    launch_convw(clsW2, DIN, 256, 256);
    launch_mma(s_MH, s_ML, 256, clsb2, nullptr, out, nullptr, nullptr, DIN, MDN, DIN, 0, T_DEC);
    zero_t0_kernel<<<(BATCH * DIN + 255) / 256, 256>>>(out);
}

// round 13
// speedup vs baseline: 1.0300x; 1.0161x over previous
#include <cuda_runtime.h>
#include <cuda_bf16.h>
#include <cstdint>

typedef unsigned long long ull;

// ---------------- problem constants ----------------
#define BATCH 64
#define DIN   176
#define HID   512
#define G4    2048          // 4*HID
#define T_ENC 1025          // 1 + 1024
#define T_DEC 1023          // TTGT - 1
#define MROWS_MAX (BATCH * T_ENC)   // 65600
#define MD_ROWS   (BATCH * T_DEC)   // 65472

// ---------------- scratch (static device globals; no cudaMalloc allowed) ----
__device__ float g_gx [(size_t)MROWS_MAX * G4];    // gx buffer (stream A)
__device__ float g_gx2[(size_t)MROWS_MAX * G4];    // gx buffer (overlapped dec L0)
#define ABUF_ROWS (MROWS_MAX + 128)
__device__ __nv_bfloat16 g_AH[(size_t)ABUF_ROWS * 512];   // A operand hi
__device__ __nv_bfloat16 g_AL[(size_t)ABUF_ROWS * 512];   // A operand lo
#define YBUF_ROWS (MD_ROWS + 128)
__device__ __nv_bfloat16 g_YH[(size_t)YBUF_ROWS * 192];   // dec input hi
__device__ __nv_bfloat16 g_YL[(size_t)YBUF_ROWS * 192];   // dec input lo
#define MBUF_ROWS (MD_ROWS + 128)
__device__ __nv_bfloat16 g_MH[(size_t)MBUF_ROWS * 256];   // hmid hi
__device__ __nv_bfloat16 g_ML[(size_t)MBUF_ROWS * 256];   // hmid lo
#define WSLOT (2048 * 512)
__device__ __nv_bfloat16 g_WHb[6 * WSLOT];                // W hi, 6 slots
__device__ __nv_bfloat16 g_WLb[6 * WSLOT];                // W lo, 6 slots
__device__ float g_hpub[2 * BATCH * HID];                 // packed (hi,lo) bf16 pairs
__device__ float g_hT0[BATCH * HID], g_cT0[BATCH * HID];
__device__ float g_hT1[BATCH * HID], g_cT1[BATCH * HID];
__device__ float g_hTd[BATCH * HID], g_cTd[BATCH * HID];
__device__ unsigned g_bar[4];

// ---------------- helpers ----------------
__device__ __forceinline__ void bf16_split(float v, __nv_bfloat16& hi, __nv_bfloat16& lo) {
    hi = __float2bfloat16(v);
    lo = __float2bfloat16(v - __bfloat162float(hi));
}

__device__ __forceinline__ uint32_t smem_to_u32(const void* p) {
    uint32_t a;
    asm("{ .reg .u64 t; cvta.to.shared.u64 t, %1; cvt.u32.u64 %0, t; }" : "=r"(a) : "l"(p));
    return a;
}

// HMMA m16n8k16 bf16 (non-arch-gated PTX; runs on sm_103 base target)
__device__ __forceinline__ void mma16816(float* d, const uint32_t* a, const uint32_t* b) {
    asm volatile(
        "mma.sync.aligned.m16n8k16.row.col.f32.bf16.bf16.f32 "
        "{%0,%1,%2,%3}, {%4,%5,%6,%7}, {%8,%9}, {%0,%1,%2,%3};"
        : "+f"(d[0]), "+f"(d[1]), "+f"(d[2]), "+f"(d[3])
        : "r"(a[0]), "r"(a[1]), "r"(a[2]), "r"(a[3]), "r"(b[0]), "r"(b[1]));
}

// cp.async 16B (LDGSTS; sm_80 PTX, non-gated)
__device__ __forceinline__ void cpasync16(uint32_t s, const void* g) {
    asm volatile("cp.async.cg.shared.global [%0], [%1], 16;" :: "r"(s), "l"(g));
}
#define CP_COMMIT() asm volatile("cp.async.commit_group;" ::: "memory")
#define CP_WAIT1()  asm volatile("cp.async.wait_group 1;" ::: "memory")

// ---------------- small utility kernels ----------------
__global__ void reset_bar_kernel(unsigned* bar) {
    if (threadIdx.x < 4) bar[threadIdx.x] = 0u;
}

// padded-shifted input -> bf16 hi/lo, layout [b][t][192] (cols 176..191 zero)
__global__ void pad_shift_bf16_kernel(const float* __restrict__ src,
                                      __nv_bfloat16* __restrict__ dH,
                                      __nv_bfloat16* __restrict__ dL,
                                      int Tsrc, int Tpad, int Tcopy) {
    long n = (long)BATCH * Tpad * 192;
    long i = (long)blockIdx.x * blockDim.x + threadIdx.x;
    if (i >= n) return;
    int d = (int)(i % 192);
    long bt = i / 192;
    int t = (int)(bt % Tpad);
    int b = (int)(bt / Tpad);
    float v = (d < DIN && t > 0 && t <= Tcopy) ? src[((long)b * Tsrc + (t - 1)) * DIN + d] : 0.f;
    __nv_bfloat16 hi, lo; bf16_split(v, hi, lo);
    dH[i] = hi; dL[i] = lo;
}

// W (N x K fp32) -> WH/WL (Npad x kpad bf16, zero padded)
__global__ void conv_w_kernel(const float* __restrict__ W,
                              __nv_bfloat16* __restrict__ WH, __nv_bfloat16* __restrict__ WL,
                              int N, int K, int kpad, int Npad) {
    long n = (long)Npad * kpad;
    long i = (long)blockIdx.x * blockDim.x + threadIdx.x;
    if (i >= n) return;
    int row = (int)(i / kpad), c = (int)(i % kpad);
    float v = (row < N && c < K) ? W[(size_t)row * K + c] : 0.f;
    __nv_bfloat16 hi, lo; bf16_split(v, hi, lo);
    WH[i] = hi; WL[i] = lo;
}

__global__ void zero_t0_kernel(float* __restrict__ out) {
    int i = blockIdx.x * blockDim.x + threadIdx.x;
    if (i < BATCH * DIN) {
        int b = i / DIN, d = i % DIN;
        out[(size_t)b * 1024 * DIN + d] = 0.f;
    }
}

// ---------------- HMMA GEMM (128x128 tile, cp.async 2-stage; R12 proven) ---
#define SOFF_AL  5120
#define SOFF_BH  10240
#define SOFF_BL  15360
#define STG_ELEMS 20480
#define MMA_SMEM_BYTES (2 * STG_ELEMS * 2)   // 81920

__global__ void __launch_bounds__(256, 2)
mma_gemm_kernel(const __nv_bfloat16* __restrict__ AH, const __nv_bfloat16* __restrict__ AL,
                const __nv_bfloat16* __restrict__ WH, const __nv_bfloat16* __restrict__ WL,
                int kpad, int nChunks,
                const float* __restrict__ b1, const float* __restrict__ b2,
                float* __restrict__ Cf, __nv_bfloat16* __restrict__ CH,
                __nv_bfloat16* __restrict__ CL,
                int ldC, int M, int Nreal, int relu, int remapT) {
    extern __shared__ __align__(16) __nv_bfloat16 smbuf[];
    const uint32_t sb = smem_to_u32(smbuf);

    const int tid  = threadIdx.x;
    const int wid  = tid >> 5, lane = tid & 31;
    const int g    = lane >> 2, tg = lane & 3;
    const int m0   = (wid & 3) * 32;
    const int n0   = (wid >> 2) * 64;
    const int row0 = blockIdx.y * 128;
    const int col0 = blockIdx.x * 128;

    const int lr0 = tid >> 2, lseg = tid & 3;   // loader: rows lr0, lr0+64

    float d[2][8][4];
#pragma unroll
    for (int mi = 0; mi < 2; mi++)
#pragma unroll
        for (int ni = 0; ni < 8; ni++)
#pragma unroll
            for (int q = 0; q < 4; q++) d[mi][ni][q] = 0.f;

    auto load_chunk = [&](int ch, int stg) {
        const int kbase = ch * 32;
        const uint32_t base = sb + stg * (STG_ELEMS * 2);
#pragma unroll
        for (int i = 0; i < 2; i++) {
            int r = lr0 + i * 64;
            size_t ga = (size_t)(row0 + r) * kpad + kbase + lseg * 8;
            size_t gb = (size_t)(col0 + r) * kpad + kbase + lseg * 8;
            uint32_t so = base + (r * 40 + lseg * 8) * 2;
            cpasync16(so, AH + ga);
            cpasync16(so + SOFF_AL * 2, AL + ga);
            cpasync16(so + SOFF_BH * 2, WH + gb);
            cpasync16(so + SOFF_BL * 2, WL + gb);
        }
    };

    load_chunk(0, 0);
    CP_COMMIT();

    for (int ch = 0; ch < nChunks; ch++) {
        const int cur = ch & 1;
        if (ch + 1 < nChunks) load_chunk(ch + 1, cur ^ 1);
        CP_COMMIT();
        CP_WAIT1();
        __syncthreads();

        const __nv_bfloat16* sAH = smbuf + cur * STG_ELEMS;
        const __nv_bfloat16* sAL = sAH + SOFF_AL;
        const __nv_bfloat16* sBH = smbuf + cur * STG_ELEMS + SOFF_BH;
        const __nv_bfloat16* sBL = smbuf + cur * STG_ELEMS + SOFF_BL;

#pragma unroll
        for (int ks = 0; ks < 2; ks++) {
            const int kb = ks * 16;
            uint32_t aH[2][4], aL[2][4];
#pragma unroll
            for (int mi = 0; mi < 2; mi++) {
                int r = m0 + mi * 16 + g;
                aH[mi][0] = *(const uint32_t*)&sAH[r * 40 + kb + 2 * tg];
                aH[mi][1] = *(const uint32_t*)&sAH[(r + 8) * 40 + kb + 2 * tg];
                aH[mi][2] = *(const uint32_t*)&sAH[r * 40 + kb + 2 * tg + 8];
                aH[mi][3] = *(const uint32_t*)&sAH[(r + 8) * 40 + kb + 2 * tg + 8];
                aL[mi][0] = *(const uint32_t*)&sAL[r * 40 + kb + 2 * tg];
                aL[mi][1] = *(const uint32_t*)&sAL[(r + 8) * 40 + kb + 2 * tg];
                aL[mi][2] = *(const uint32_t*)&sAL[r * 40 + kb + 2 * tg + 8];
                aL[mi][3] = *(const uint32_t*)&sAL[(r + 8) * 40 + kb + 2 * tg + 8];
            }
#pragma unroll
            for (int ni = 0; ni < 8; ni++) {
                int r = n0 + ni * 8 + g;
                uint32_t bH[2], bL[2];
                bH[0] = *(const uint32_t*)&sBH[r * 40 + kb + 2 * tg];
                bH[1] = *(const uint32_t*)&sBH[r * 40 + kb + 2 * tg + 8];
                bL[0] = *(const uint32_t*)&sBL[r * 40 + kb + 2 * tg];
                bL[1] = *(const uint32_t*)&sBL[r * 40 + kb + 2 * tg + 8];
#pragma unroll
                for (int mi = 0; mi < 2; mi++) {
                    mma16816(d[mi][ni], aH[mi], bH);
                    mma16816(d[mi][ni], aL[mi], bH);
                    mma16816(d[mi][ni], aH[mi], bL);
                }
            }
        }
        __syncthreads();
    }

    // epilogue: bias/relu, optional remap, fp32 and/or bf16 hi/lo stores
#pragma unroll
    for (int mi = 0; mi < 2; mi++) {
#pragma unroll
        for (int rr = 0; rr < 2; rr++) {
            int r = row0 + m0 + mi * 16 + g + rr * 8;
            if (r >= M) continue;
            size_t rowbase;
            if (remapT > 0) {
                int bb = r / remapT, tt = r - bb * remapT;
                rowbase = ((size_t)bb * (remapT + 1) + tt + 1) * (size_t)ldC;
            } else {
                rowbase = (size_t)r * ldC;
            }
#pragma unroll
            for (int ni = 0; ni < 8; ni++) {
#pragma unroll
                for (int cc = 0; cc < 2; cc++) {
                    int col = col0 + n0 + ni * 8 + 2 * tg + cc;
                    if (col >= Nreal) continue;
                    float v = d[mi][ni][rr * 2 + cc]
                            + (b1 ? __ldg(b1 + col) : 0.f) + (b2 ? __ldg(b2 + col) : 0.f);
                    if (relu) v = fmaxf(v, 0.f);
                    if (Cf) Cf[rowbase + col] = v;
                    if (CH) {
                        __nv_bfloat16 hi, lo; bf16_split(v, hi, lo);
                        CH[rowbase + col] = hi;
                        CL[rowbase + col] = lo;
                    }
                }
            }
        }
    }
}

// ---------------- persistent LSTM scan (round-11, unchanged) ---------------
#define SW_K     520
#define SOFF_WL2 (64 * SW_K)               // 33280
#define SOFF_HH  (2 * 64 * SW_K)           // 66560
#define SOFF_HL  (SOFF_HH + 16 * SW_K)     // 74880
#define SCAN_BF16_ELEMS (SOFF_HL + 16 * SW_K)   // 83200
#define SCAN_RED_FLOATS (8 * 16 * 66)      // 8448
#define SCAN_SMEM_BYTES (SCAN_BF16_ELEMS * 2 + SCAN_RED_FLOATS * 4)  // 200192

__device__ __forceinline__ float sigf(float x) { return 1.f / (1.f + expf(-x)); }

__device__ __forceinline__ void group_barrier(unsigned* bar, int bg, unsigned target) {
    __threadfence();
    __syncthreads();
    if (threadIdx.x == 0) {
        atomicAdd(&bar[bg], 1u);
        while (atomicAdd(&bar[bg], 0u) < target) { }
        __threadfence();
    }
    __syncthreads();
}

__global__ void __launch_bounds__(256, 1)
lstm_scan_kernel(const float* __restrict__ gx, const float* __restrict__ Whh,
                 const float* __restrict__ h0, const float* __restrict__ c0,
                 __nv_bfloat16* __restrict__ hsH, __nv_bfloat16* __restrict__ hsL,
                 float* __restrict__ hT_out, float* __restrict__ cT_out,
                 float* __restrict__ hpub, unsigned* __restrict__ bar, int T) {
    extern __shared__ __align__(16) __nv_bfloat16 sm[];
    __nv_bfloat16* sWH = sm;                 // [64][520] (used once)
    __nv_bfloat16* sWL = sm + SOFF_WL2;      // [64][520] (used once)
    __nv_bfloat16* sHH = sm + SOFF_HH;       // [16][520]
    __nv_bfloat16* sHL = sm + SOFF_HL;       // [16][520]
    float* red = (float*)(sm + SCAN_BF16_ELEMS);  // [8][16][66]

    uint32_t* hpub32 = (uint32_t*)hpub;      // packed (hi | lo<<16) bf16 pairs

    const int tid = threadIdx.x;
    const int bg = blockIdx.x >> 5;
    const int ht = blockIdx.x & 31;
    const int B0 = bg * 16;
    const int J0 = ht * 16;
    const int w = tid >> 5;
    const int lane = tid & 31;
    const int g = lane >> 2, tg = lane & 3;

    // ---- load + split Whh slice into smem (once); n = gate*16 + j ----
    for (int idx = tid; idx < 64 * 512; idx += 256) {
        int n = idx >> 9, k = idx & 511;
        float v = Whh[(size_t)((n >> 4) * 512 + J0 + (n & 15)) * 512 + k];
        __nv_bfloat16 hi, lo; bf16_split(v, hi, lo);
        sWH[n * SW_K + k] = hi;
        sWL[n * SW_K + k] = lo;
    }

    // ---- init states ----
    const int ub = tid >> 4;            // batch within tile (0..15)
    const int uj = tid & 15;            // hidden within tile (0..15)
    float cval = c0 ? c0[(B0 + ub) * 512 + J0 + uj] : 0.f;
    float hval = h0 ? h0[(B0 + ub) * 512 + J0 + uj] : 0.f;
    {
        __nv_bfloat16 hi, lo; bf16_split(hval, hi, lo);
        uint32_t hp = (uint32_t)__bfloat16_as_ushort(hi)
                    | ((uint32_t)__bfloat16_as_ushort(lo) << 16);
        hpub32[32768 + (B0 + ub) * 512 + J0 + uj] = hp;   // parity-1 feeds t=0
    }

    unsigned nbar = 1;
    group_barrier(bar, bg, nbar * 32);   // covers weight-fill visibility too

    // ---- hoist B (weight) fragments into registers: [ks][ni][2] ----
    uint32_t rbH[4][8][2], rbL[4][8][2];
#pragma unroll
    for (int ks = 0; ks < 4; ks++) {
        const int kb = w * 64 + ks * 16;
#pragma unroll
        for (int ni = 0; ni < 8; ni++) {
            int r = ni * 8 + g;
            rbH[ks][ni][0] = *(const uint32_t*)&sWH[r * SW_K + kb + 2 * tg];
            rbH[ks][ni][1] = *(const uint32_t*)&sWH[r * SW_K + kb + 2 * tg + 8];
            rbL[ks][ni][0] = *(const uint32_t*)&sWL[r * SW_K + kb + 2 * tg];
            rbL[ks][ni][1] = *(const uint32_t*)&sWL[r * SW_K + kb + 2 * tg + 8];
        }
    }

    const int p1b = tid & 15;
    const int p1k = tid >> 4;

    const float* gxrow = gx + ((size_t)(B0 + ub) * T) * G4 + J0 + uj;
    __nv_bfloat16* hH = hsH ? hsH + ((size_t)(B0 + ub) * T) * 512 + J0 + uj : nullptr;
    __nv_bfloat16* hL = hsL ? hsL + ((size_t)(B0 + ub) * T) * 512 + J0 + uj : nullptr;

    for (int t = 0; t < T; ++t) {
        float pgi = gxrow[0], pgf = gxrow[512], pgg = gxrow[1024], pgo = gxrow[1536];

        const uint32_t* hsrc = hpub32 + (((t + 1) & 1) << 15);

        // phase 1: load packed h pairs, de-interleave hi/lo via PRMT
#pragma unroll
        for (int i = 0; i < 8; ++i) {
            int kq = p1k + (i << 4);                  // uint4 index 0..127
            uint4 hv = __ldcg((const uint4*)(hsrc + (B0 + p1b) * 512 + (kq << 2)));
            int base = p1b * SW_K + (kq << 2);
            *(uint32_t*)&sHH[base]     = __byte_perm(hv.x, hv.y, 0x5410);
            *(uint32_t*)&sHL[base]     = __byte_perm(hv.x, hv.y, 0x7632);
            *(uint32_t*)&sHH[base + 2] = __byte_perm(hv.z, hv.w, 0x5410);
            *(uint32_t*)&sHL[base + 2] = __byte_perm(hv.z, hv.w, 0x7632);
        }
        __syncthreads();

        // phase 2: HMMA m16 x n64 x k64, weights from registers
        float c[8][4];
#pragma unroll
        for (int ni = 0; ni < 8; ni++)
#pragma unroll
            for (int q = 0; q < 4; q++) c[ni][q] = 0.f;

        const int kb0 = w * 64;
#pragma unroll
        for (int ks = 0; ks < 4; ks++) {
            const int kb = kb0 + ks * 16;
            uint32_t aH[4], aL[4];
            aH[0] = *(const uint32_t*)&sHH[g * SW_K + kb + 2 * tg];
            aH[1] = *(const uint32_t*)&sHH[(g + 8) * SW_K + kb + 2 * tg];
            aH[2] = *(const uint32_t*)&sHH[g * SW_K + kb + 2 * tg + 8];
            aH[3] = *(const uint32_t*)&sHH[(g + 8) * SW_K + kb + 2 * tg + 8];
            aL[0] = *(const uint32_t*)&sHL[g * SW_K + kb + 2 * tg];
            aL[1] = *(const uint32_t*)&sHL[(g + 8) * SW_K + kb + 2 * tg];
            aL[2] = *(const uint32_t*)&sHL[g * SW_K + kb + 2 * tg + 8];
            aL[3] = *(const uint32_t*)&sHL[(g + 8) * SW_K + kb + 2 * tg + 8];
#pragma unroll
            for (int ni = 0; ni < 8; ni++) {
                mma16816(c[ni], aH, rbH[ks][ni]);
                mma16816(c[ni], aL, rbH[ks][ni]);
                mma16816(c[ni], aH, rbL[ks][ni]);
            }
        }

        // phase 3: fragments -> red[w][m][n] (pad 66)
#pragma unroll
        for (int ni = 0; ni < 8; ni++) {
            int nn = ni * 8 + 2 * tg;
            float2 v01 = make_float2(c[ni][0], c[ni][1]);
            float2 v23 = make_float2(c[ni][2], c[ni][3]);
            *(float2*)&red[w * 1056 + g * 66 + nn] = v01;
            *(float2*)&red[w * 1056 + (g + 8) * 66 + nn] = v23;
        }
        __syncthreads();

        // phase 4: reduce 8 k-slices, add gx, LSTM cell (thread = (ub,uj))
        float gsum[4];
#pragma unroll
        for (int gt = 0; gt < 4; gt++) {
            float v = 0.f;
#pragma unroll
            for (int s2 = 0; s2 < 8; s2++)
                v += red[s2 * 1056 + ub * 66 + gt * 16 + uj];
            gsum[gt] = v;
        }
        float gi = gsum[0] + pgi, gf = gsum[1] + pgf;
        float gg = gsum[2] + pgg, go = gsum[3] + pgo;

        float ig = sigf(gi), fg = sigf(gf), og_ = sigf(go), gt_ = tanhf(gg);
        cval = fg * cval + ig * gt_;
        hval = og_ * tanhf(cval);

        __nv_bfloat16 hi, lo; bf16_split(hval, hi, lo);
        uint32_t hp = (uint32_t)__bfloat16_as_ushort(hi)
                    | ((uint32_t)__bfloat16_as_ushort(lo) << 16);
        hpub32[((t & 1) << 15) + (B0 + ub) * 512 + J0 + uj] = hp;
        if (hH) { *hH = hi; *hL = lo; hH += 512; hL += 512; }
        gxrow += G4;

        ++nbar;
        group_barrier(bar, bg, nbar * 32);
    }

    hT_out[(B0 + ub) * 512 + J0 + uj] = hval;
    cT_out[(B0 + ub) * 512 + J0 + uj] = cval;
}

// ---------------- host orchestration ----------------
static __nv_bfloat16 *s_AH, *s_AL, *s_YH, *s_YL, *s_MH, *s_ML, *s_WH, *s_WL;

static void launch_mma_s(cudaStream_t st,
                         const __nv_bfloat16* AH, const __nv_bfloat16* AL,
                         const __nv_bfloat16* WHp, const __nv_bfloat16* WLp,
                         int kpad, const float* b1, const float* b2,
                         float* Cf, __nv_bfloat16* CH, __nv_bfloat16* CL,
                         int ldC, int M, int Nreal, int relu, int remapT) {
    int mt = (M + 127) / 128;
    int nt = (Nreal + 127) / 128;
    int nChunks = kpad / 32;
    mma_gemm_kernel<<<dim3(nt, mt), 256, MMA_SMEM_BYTES, st>>>(
        AH, AL, WHp, WLp, kpad, nChunks, b1, b2, Cf, CH, CL, ldC, M, Nreal, relu, remapT);
}

static void launch_convw_s(cudaStream_t st, const float* W, int N, int K, int kpad,
                           __nv_bfloat16* WHp, __nv_bfloat16* WLp) {
    int Npad = ((N + 63) / 64) * 64;
    long n = (long)Npad * kpad;
    conv_w_kernel<<<(int)((n + 255) / 256), 256, 0, st>>>(W, WHp, WLp, N, K, kpad, Npad);
}

extern "C" void kernel_launch(void* const* d_in, const int* in_sizes, int n_in,
                              void* d_out, int out_size) {
    (void)in_sizes; (void)n_in; (void)out_size;
    const float* x     = (const float*)d_in[0];
    const float* y     = (const float*)d_in[1];
    const float* eWih0 = (const float*)d_in[2];
    const float* eWhh0 = (const float*)d_in[3];
    const float* ebih0 = (const float*)d_in[4];
    const float* ebhh0 = (const float*)d_in[5];
    const float* eWih1 = (const float*)d_in[6];
    const float* eWhh1 = (const float*)d_in[7];
    const float* ebih1 = (const float*)d_in[8];
    const float* ebhh1 = (const float*)d_in[9];
    const float* dWih0 = (const float*)d_in[10];
    const float* dWhh0 = (const float*)d_in[11];
    const float* dbih0 = (const float*)d_in[12];
    const float* dbhh0 = (const float*)d_in[13];
    const float* dWih1 = (const float*)d_in[14];
    const float* dWhh1 = (const float*)d_in[15];
    const float* dbih1 = (const float*)d_in[16];
    const float* dbhh1 = (const float*)d_in[17];
    const float* clsW1 = (const float*)d_in[18];
    const float* clsb1 = (const float*)d_in[19];
    const float* clsW2 = (const float*)d_in[20];
    const float* clsb2 = (const float*)d_in[21];
    float* out = (float*)d_out;

    // stream/event statics: created on the first (uncaptured) correctness call
    static cudaStream_t sB = nullptr;
    static cudaEvent_t evFork = nullptr, evW = nullptr, evB = nullptr;
    if (sB == nullptr) {
        cudaStreamCreateWithFlags(&sB, cudaStreamNonBlocking);
        cudaEventCreateWithFlags(&evFork, cudaEventDisableTiming);
        cudaEventCreateWithFlags(&evW, cudaEventDisableTiming);
        cudaEventCreateWithFlags(&evB, cudaEventDisableTiming);
    }

    float *gx, *gx2, *hpub, *hT0, *cT0, *hT1, *cT1, *hTd, *cTd;
    unsigned* bar;
    cudaGetSymbolAddress((void**)&gx,   g_gx);
    cudaGetSymbolAddress((void**)&gx2,  g_gx2);
    cudaGetSymbolAddress((void**)&hpub, g_hpub);
    cudaGetSymbolAddress((void**)&hT0,  g_hT0);
    cudaGetSymbolAddress((void**)&cT0,  g_cT0);
    cudaGetSymbolAddress((void**)&hT1,  g_hT1);
    cudaGetSymbolAddress((void**)&cT1,  g_cT1);
    cudaGetSymbolAddress((void**)&hTd,  g_hTd);
    cudaGetSymbolAddress((void**)&cTd,  g_cTd);
    cudaGetSymbolAddress((void**)&bar,  g_bar);
    cudaGetSymbolAddress((void**)&s_AH, g_AH);
    cudaGetSymbolAddress((void**)&s_AL, g_AL);
    cudaGetSymbolAddress((void**)&s_YH, g_YH);
    cudaGetSymbolAddress((void**)&s_YL, g_YL);
    cudaGetSymbolAddress((void**)&s_MH, g_MH);
    cudaGetSymbolAddress((void**)&s_ML, g_ML);
    cudaGetSymbolAddress((void**)&s_WH, g_WHb);
    cudaGetSymbolAddress((void**)&s_WL, g_WLb);

    cudaFuncSetAttribute(lstm_scan_kernel,
                         cudaFuncAttributeMaxDynamicSharedMemorySize, SCAN_SMEM_BYTES);
    cudaFuncSetAttribute(mma_gemm_kernel,
                         cudaFuncAttributeMaxDynamicSharedMemorySize, MMA_SMEM_BYTES);

    const int ME  = MROWS_MAX;   // 65600
    const int MDN = MD_ROWS;     // 65472

    // W slots: 0=eWih0, 1=dWih0, 2=eWih1, 3=dWih1, 4=clsW1, 5=clsW2
    __nv_bfloat16 *WH0 = s_WH,             *WL0 = s_WL;
    __nv_bfloat16 *WH1 = s_WH + 1 * WSLOT, *WL1 = s_WL + 1 * WSLOT;
    __nv_bfloat16 *WH2 = s_WH + 2 * WSLOT, *WL2 = s_WL + 2 * WSLOT;
    __nv_bfloat16 *WH3 = s_WH + 3 * WSLOT, *WL3 = s_WL + 3 * WSLOT;
    __nv_bfloat16 *WH4 = s_WH + 4 * WSLOT, *WL4 = s_WL + 4 * WSLOT;
    __nv_bfloat16 *WH5 = s_WH + 5 * WSLOT, *WL5 = s_WL + 5 * WSLOT;

    // -------- stream A: encoder layer 0 --------
    {
        long n = (long)BATCH * T_ENC * 192;
        pad_shift_bf16_kernel<<<(int)((n + 255) / 256), 256>>>(x, s_AH, s_AL, 1024, T_ENC, 1024);
    }
    launch_convw_s(0, eWih0, G4, DIN, 192, WH0, WL0);
    launch_mma_s(0, s_AH, s_AL, WH0, WL0, 192, ebih0, ebhh0,
                 gx, nullptr, nullptr, G4, ME, G4, 0, 0);
    cudaEventRecord(evFork, 0);

    // -------- stream B (overlapped with encoder scans) --------
    cudaStreamWaitEvent(sB, evFork, 0);
    {
        long n = (long)BATCH * T_DEC * 192;
        pad_shift_bf16_kernel<<<(int)((n + 255) / 256), 256, 0, sB>>>(y, s_YH, s_YL, 1024, T_DEC, 1022);
    }
    launch_convw_s(sB, dWih0, G4, DIN, 192, WH1, WL1);
    launch_convw_s(sB, eWih1, G4, HID, 512, WH2, WL2);
    launch_convw_s(sB, dWih1, G4, HID, 512, WH3, WL3);
    launch_convw_s(sB, clsW1, 256, HID, 512, WH4, WL4);
    launch_convw_s(sB, clsW2, DIN, 256, 256, WH5, WL5);
    cudaEventRecord(evW, sB);
    launch_mma_s(sB, s_YH, s_YL, WH1, WL1, 192, dbih0, dbhh0,
                 gx2, nullptr, nullptr, G4, MDN, G4, 0, 0);
    cudaEventRecord(evB, sB);

    // -------- stream A continues: encoder scans --------
    reset_bar_kernel<<<1, 32>>>(bar);
    lstm_scan_kernel<<<128, 256, SCAN_SMEM_BYTES>>>(gx, eWhh0, nullptr, nullptr,
                                                    s_AH, s_AL, hT0, cT0, hpub, bar, T_ENC);
    cudaStreamWaitEvent(0, evW, 0);
    launch_mma_s(0, s_AH, s_AL, WH2, WL2, 512, ebih1, ebhh1,
                 gx, nullptr, nullptr, G4, ME, G4, 0, 0);
    reset_bar_kernel<<<1, 32>>>(bar);
    lstm_scan_kernel<<<128, 256, SCAN_SMEM_BYTES>>>(gx, eWhh1, nullptr, nullptr,
                                                    nullptr, nullptr, hT1, cT1, hpub, bar, T_ENC);

    // -------- decoder --------
    cudaStreamWaitEvent(0, evB, 0);
    reset_bar_kernel<<<1, 32>>>(bar);
    lstm_scan_kernel<<<128, 256, SCAN_SMEM_BYTES>>>(gx2, dWhh0, hT0, cT0,
                                                    s_AH, s_AL, hTd, cTd, hpub, bar, T_DEC);
    launch_mma_s(0, s_AH, s_AL, WH3, WL3, 512, dbih1, dbhh1,
                 gx, nullptr, nullptr, G4, MDN, G4, 0, 0);
    reset_bar_kernel<<<1, 32>>>(bar);
    lstm_scan_kernel<<<128, 256, SCAN_SMEM_BYTES>>>(gx, dWhh1, hT1, cT1,
                                                    s_AH, s_AL, hTd, cTd, hpub, bar, T_DEC);

    // -------- classifier --------
    launch_mma_s(0, s_AH, s_AL, WH4, WL4, 512, clsb1, nullptr,
                 nullptr, s_MH, s_ML, 256, MDN, 256, 1, 0);
    launch_mma_s(0, s_MH, s_ML, WH5, WL5, 256, clsb2, nullptr,
                 out, nullptr, nullptr, DIN, MDN, DIN, 0, T_DEC);
    zero_t0_kernel<<<(BATCH * DIN + 255) / 256, 256>>>(out);
}

// round 14
// speedup vs baseline: 1.0374x; 1.0072x over previous
#include <cuda_runtime.h>
#include <cuda_bf16.h>
#include <cstdint>

typedef unsigned long long ull;

// ---------------- problem constants ----------------
#define BATCH 64
#define DIN   176
#define HID   512
#define G4    2048          // 4*HID
#define T_ENC 1025          // 1 + 1024
#define T_DEC 1023          // TTGT - 1
#define MROWS_MAX (BATCH * T_ENC)   // 65600
#define MD_ROWS   (BATCH * T_DEC)   // 65472

// ---------------- scratch (static device globals; no cudaMalloc allowed) ----
__device__ float g_gx [(size_t)MROWS_MAX * G4];    // gx buffer (stream A)
__device__ float g_gx2[(size_t)MROWS_MAX * G4];    // gx buffer (overlapped dec L0)
#define ABUF_ROWS (MROWS_MAX + 128)
__device__ __nv_bfloat16 g_AH[(size_t)ABUF_ROWS * 512];   // A operand hi
__device__ __nv_bfloat16 g_AL[(size_t)ABUF_ROWS * 512];   // A operand lo
#define YBUF_ROWS (MD_ROWS + 128)
__device__ __nv_bfloat16 g_YH[(size_t)YBUF_ROWS * 192];   // dec input hi
__device__ __nv_bfloat16 g_YL[(size_t)YBUF_ROWS * 192];   // dec input lo
#define MBUF_ROWS (MD_ROWS + 128)
__device__ __nv_bfloat16 g_MH[(size_t)MBUF_ROWS * 256];   // hmid hi
__device__ __nv_bfloat16 g_ML[(size_t)MBUF_ROWS * 256];   // hmid lo
#define WSLOT (2048 * 512)
__device__ __nv_bfloat16 g_WHb[6 * WSLOT];                // W hi, 6 slots
__device__ __nv_bfloat16 g_WLb[6 * WSLOT];                // W lo, 6 slots
__device__ float g_hpub[2 * BATCH * HID];                 // packed (hi,lo) bf16 pairs
__device__ float g_hT0[BATCH * HID], g_cT0[BATCH * HID];
__device__ float g_hT1[BATCH * HID], g_cT1[BATCH * HID];
__device__ float g_hTd[BATCH * HID], g_cTd[BATCH * HID];
__device__ unsigned g_bar[16];                            // 4 slots x 4 scans

// ---------------- helpers ----------------
__device__ __forceinline__ void bf16_split(float v, __nv_bfloat16& hi, __nv_bfloat16& lo) {
    hi = __float2bfloat16(v);
    lo = __float2bfloat16(v - __bfloat162float(hi));
}

__device__ __forceinline__ uint32_t smem_to_u32(const void* p) {
    uint32_t a;
    asm("{ .reg .u64 t; cvta.to.shared.u64 t, %1; cvt.u32.u64 %0, t; }" : "=r"(a) : "l"(p));
    return a;
}

// HMMA m16n8k16 bf16 (non-arch-gated PTX; runs on sm_103 base target)
__device__ __forceinline__ void mma16816(float* d, const uint32_t* a, const uint32_t* b) {
    asm volatile(
        "mma.sync.aligned.m16n8k16.row.col.f32.bf16.bf16.f32 "
        "{%0,%1,%2,%3}, {%4,%5,%6,%7}, {%8,%9}, {%0,%1,%2,%3};"
        : "+f"(d[0]), "+f"(d[1]), "+f"(d[2]), "+f"(d[3])
        : "r"(a[0]), "r"(a[1]), "r"(a[2]), "r"(a[3]), "r"(b[0]), "r"(b[1]));
}

// cp.async 16B (LDGSTS; sm_80 PTX, non-gated)
__device__ __forceinline__ void cpasync16(uint32_t s, const void* g) {
    asm volatile("cp.async.cg.shared.global [%0], [%1], 16;" :: "r"(s), "l"(g));
}
#define CP_COMMIT() asm volatile("cp.async.commit_group;" ::: "memory")
#define CP_WAIT1()  asm volatile("cp.async.wait_group 1;" ::: "memory")

// ---------------- small utility kernels ----------------
__global__ void reset_bar_kernel(unsigned* bar) {
    if (threadIdx.x < 16) bar[threadIdx.x] = 0u;
}

// padded-shifted input -> bf16 hi/lo, layout [b][t][192] (cols 176..191 zero)
__global__ void pad_shift_bf16_kernel(const float* __restrict__ src,
                                      __nv_bfloat16* __restrict__ dH,
                                      __nv_bfloat16* __restrict__ dL,
                                      int Tsrc, int Tpad, int Tcopy) {
    long n = (long)BATCH * Tpad * 192;
    long i = (long)blockIdx.x * blockDim.x + threadIdx.x;
    if (i >= n) return;
    int d = (int)(i % 192);
    long bt = i / 192;
    int t = (int)(bt % Tpad);
    int b = (int)(bt / Tpad);
    float v = (d < DIN && t > 0 && t <= Tcopy) ? src[((long)b * Tsrc + (t - 1)) * DIN + d] : 0.f;
    __nv_bfloat16 hi, lo; bf16_split(v, hi, lo);
    dH[i] = hi; dL[i] = lo;
}

// W (N x K fp32) -> WH/WL (Npad x kpad bf16, zero padded)
__global__ void conv_w_kernel(const float* __restrict__ W,
                              __nv_bfloat16* __restrict__ WH, __nv_bfloat16* __restrict__ WL,
                              int N, int K, int kpad, int Npad) {
    long n = (long)Npad * kpad;
    long i = (long)blockIdx.x * blockDim.x + threadIdx.x;
    if (i >= n) return;
    int row = (int)(i / kpad), c = (int)(i % kpad);
    float v = (row < N && c < K) ? W[(size_t)row * K + c] : 0.f;
    __nv_bfloat16 hi, lo; bf16_split(v, hi, lo);
    WH[i] = hi; WL[i] = lo;
}

__global__ void zero_t0_kernel(float* __restrict__ out) {
    int i = blockIdx.x * blockDim.x + threadIdx.x;
    if (i < BATCH * DIN) {
        int b = i / DIN, d = i % DIN;
        out[(size_t)b * 1024 * DIN + d] = 0.f;
    }
}

// ---------------- HMMA GEMM (128x128 tile, cp.async 2-stage; R12 proven) ---
#define SOFF_AL  5120
#define SOFF_BH  10240
#define SOFF_BL  15360
#define STG_ELEMS 20480
#define MMA_SMEM_BYTES (2 * STG_ELEMS * 2)   // 81920

__global__ void __launch_bounds__(256, 2)
mma_gemm_kernel(const __nv_bfloat16* __restrict__ AH, const __nv_bfloat16* __restrict__ AL,
                const __nv_bfloat16* __restrict__ WH, const __nv_bfloat16* __restrict__ WL,
                int kpad, int nChunks,
                const float* __restrict__ b1, const float* __restrict__ b2,
                float* __restrict__ Cf, __nv_bfloat16* __restrict__ CH,
                __nv_bfloat16* __restrict__ CL,
                int ldC, int M, int Nreal, int relu, int remapT) {
    extern __shared__ __align__(16) __nv_bfloat16 smbuf[];
    const uint32_t sb = smem_to_u32(smbuf);

    const int tid  = threadIdx.x;
    const int wid  = tid >> 5, lane = tid & 31;
    const int g    = lane >> 2, tg = lane & 3;
    const int m0   = (wid & 3) * 32;
    const int n0   = (wid >> 2) * 64;
    const int row0 = blockIdx.y * 128;
    const int col0 = blockIdx.x * 128;

    const int lr0 = tid >> 2, lseg = tid & 3;   // loader: rows lr0, lr0+64

    float d[2][8][4];
#pragma unroll
    for (int mi = 0; mi < 2; mi++)
#pragma unroll
        for (int ni = 0; ni < 8; ni++)
#pragma unroll
            for (int q = 0; q < 4; q++) d[mi][ni][q] = 0.f;

    auto load_chunk = [&](int ch, int stg) {
        const int kbase = ch * 32;
        const uint32_t base = sb + stg * (STG_ELEMS * 2);
#pragma unroll
        for (int i = 0; i < 2; i++) {
            int r = lr0 + i * 64;
            size_t ga = (size_t)(row0 + r) * kpad + kbase + lseg * 8;
            size_t gb = (size_t)(col0 + r) * kpad + kbase + lseg * 8;
            uint32_t so = base + (r * 40 + lseg * 8) * 2;
            cpasync16(so, AH + ga);
            cpasync16(so + SOFF_AL * 2, AL + ga);
            cpasync16(so + SOFF_BH * 2, WH + gb);
            cpasync16(so + SOFF_BL * 2, WL + gb);
        }
    };

    load_chunk(0, 0);
    CP_COMMIT();

    for (int ch = 0; ch < nChunks; ch++) {
        const int cur = ch & 1;
        if (ch + 1 < nChunks) load_chunk(ch + 1, cur ^ 1);
        CP_COMMIT();
        CP_WAIT1();
        __syncthreads();

        const __nv_bfloat16* sAH = smbuf + cur * STG_ELEMS;
        const __nv_bfloat16* sAL = sAH + SOFF_AL;
        const __nv_bfloat16* sBH = smbuf + cur * STG_ELEMS + SOFF_BH;
        const __nv_bfloat16* sBL = smbuf + cur * STG_ELEMS + SOFF_BL;

#pragma unroll
        for (int ks = 0; ks < 2; ks++) {
            const int kb = ks * 16;
            uint32_t aH[2][4], aL[2][4];
#pragma unroll
            for (int mi = 0; mi < 2; mi++) {
                int r = m0 + mi * 16 + g;
                aH[mi][0] = *(const uint32_t*)&sAH[r * 40 + kb + 2 * tg];
                aH[mi][1] = *(const uint32_t*)&sAH[(r + 8) * 40 + kb + 2 * tg];
                aH[mi][2] = *(const uint32_t*)&sAH[r * 40 + kb + 2 * tg + 8];
                aH[mi][3] = *(const uint32_t*)&sAH[(r + 8) * 40 + kb + 2 * tg + 8];
                aL[mi][0] = *(const uint32_t*)&sAL[r * 40 + kb + 2 * tg];
                aL[mi][1] = *(const uint32_t*)&sAL[(r + 8) * 40 + kb + 2 * tg];
                aL[mi][2] = *(const uint32_t*)&sAL[r * 40 + kb + 2 * tg + 8];
                aL[mi][3] = *(const uint32_t*)&sAL[(r + 8) * 40 + kb + 2 * tg + 8];
            }
#pragma unroll
            for (int ni = 0; ni < 8; ni++) {
                int r = n0 + ni * 8 + g;
                uint32_t bH[2], bL[2];
                bH[0] = *(const uint32_t*)&sBH[r * 40 + kb + 2 * tg];
                bH[1] = *(const uint32_t*)&sBH[r * 40 + kb + 2 * tg + 8];
                bL[0] = *(const uint32_t*)&sBL[r * 40 + kb + 2 * tg];
                bL[1] = *(const uint32_t*)&sBL[r * 40 + kb + 2 * tg + 8];
#pragma unroll
                for (int mi = 0; mi < 2; mi++) {
                    mma16816(d[mi][ni], aH[mi], bH);
                    mma16816(d[mi][ni], aL[mi], bH);
                    mma16816(d[mi][ni], aH[mi], bL);
                }
            }
        }
        __syncthreads();
    }

    // epilogue: bias/relu, optional remap, fp32 and/or bf16 hi/lo stores
#pragma unroll
    for (int mi = 0; mi < 2; mi++) {
#pragma unroll
        for (int rr = 0; rr < 2; rr++) {
            int r = row0 + m0 + mi * 16 + g + rr * 8;
            if (r >= M) continue;
            size_t rowbase;
            if (remapT > 0) {
                int bb = r / remapT, tt = r - bb * remapT;
                rowbase = ((size_t)bb * (remapT + 1) + tt + 1) * (size_t)ldC;
            } else {
                rowbase = (size_t)r * ldC;
            }
#pragma unroll
            for (int ni = 0; ni < 8; ni++) {
#pragma unroll
                for (int cc = 0; cc < 2; cc++) {
                    int col = col0 + n0 + ni * 8 + 2 * tg + cc;
                    if (col >= Nreal) continue;
                    float v = d[mi][ni][rr * 2 + cc]
                            + (b1 ? __ldg(b1 + col) : 0.f) + (b2 ? __ldg(b2 + col) : 0.f);
                    if (relu) v = fmaxf(v, 0.f);
                    if (Cf) Cf[rowbase + col] = v;
                    if (CH) {
                        __nv_bfloat16 hi, lo; bf16_split(v, hi, lo);
                        CH[rowbase + col] = hi;
                        CL[rowbase + col] = lo;
                    }
                }
            }
        }
    }
}

// ---------------- persistent LSTM scan (round-11 core, nanosleep poll) -----
#define SW_K     520
#define SOFF_WL2 (64 * SW_K)               // 33280
#define SOFF_HH  (2 * 64 * SW_K)           // 66560
#define SOFF_HL  (SOFF_HH + 16 * SW_K)     // 74880
#define SCAN_BF16_ELEMS (SOFF_HL + 16 * SW_K)   // 83200
#define SCAN_RED_FLOATS (8 * 16 * 66)      // 8448
#define SCAN_SMEM_BYTES (SCAN_BF16_ELEMS * 2 + SCAN_RED_FLOATS * 4)  // 200192

__device__ __forceinline__ float sigf(float x) { return 1.f / (1.f + expf(-x)); }

__device__ __forceinline__ void group_barrier(unsigned* bar, int bg, unsigned target) {
    __threadfence();
    __syncthreads();
    if (threadIdx.x == 0) {
        atomicAdd(&bar[bg], 1u);
        while (atomicAdd(&bar[bg], 0u) < target) { __nanosleep(64); }
        __threadfence();
    }
    __syncthreads();
}

__global__ void __launch_bounds__(256, 1)
lstm_scan_kernel(const float* __restrict__ gx, const float* __restrict__ Whh,
                 const float* __restrict__ h0, const float* __restrict__ c0,
                 __nv_bfloat16* __restrict__ hsH, __nv_bfloat16* __restrict__ hsL,
                 float* __restrict__ hT_out, float* __restrict__ cT_out,
                 float* __restrict__ hpub, unsigned* __restrict__ bar, int T) {
    extern __shared__ __align__(16) __nv_bfloat16 sm[];
    __nv_bfloat16* sWH = sm;                 // [64][520] (used once)
    __nv_bfloat16* sWL = sm + SOFF_WL2;      // [64][520] (used once)
    __nv_bfloat16* sHH = sm + SOFF_HH;       // [16][520]
    __nv_bfloat16* sHL = sm + SOFF_HL;       // [16][520]
    float* red = (float*)(sm + SCAN_BF16_ELEMS);  // [8][16][66]

    uint32_t* hpub32 = (uint32_t*)hpub;      // packed (hi | lo<<16) bf16 pairs

    const int tid = threadIdx.x;
    const int bg = blockIdx.x >> 5;
    const int ht = blockIdx.x & 31;
    const int B0 = bg * 16;
    const int J0 = ht * 16;
    const int w = tid >> 5;
    const int lane = tid & 31;
    const int g = lane >> 2, tg = lane & 3;

    // ---- load + split Whh slice into smem (once); n = gate*16 + j ----
    for (int idx = tid; idx < 64 * 512; idx += 256) {
        int n = idx >> 9, k = idx & 511;
        float v = Whh[(size_t)((n >> 4) * 512 + J0 + (n & 15)) * 512 + k];
        __nv_bfloat16 hi, lo; bf16_split(v, hi, lo);
        sWH[n * SW_K + k] = hi;
        sWL[n * SW_K + k] = lo;
    }

    // ---- init states ----
    const int ub = tid >> 4;            // batch within tile (0..15)
    const int uj = tid & 15;            // hidden within tile (0..15)
    float cval = c0 ? c0[(B0 + ub) * 512 + J0 + uj] : 0.f;
    float hval = h0 ? h0[(B0 + ub) * 512 + J0 + uj] : 0.f;
    {
        __nv_bfloat16 hi, lo; bf16_split(hval, hi, lo);
        uint32_t hp = (uint32_t)__bfloat16_as_ushort(hi)
                    | ((uint32_t)__bfloat16_as_ushort(lo) << 16);
        hpub32[32768 + (B0 + ub) * 512 + J0 + uj] = hp;   // parity-1 feeds t=0
    }

    unsigned nbar = 1;
    group_barrier(bar, bg, nbar * 32);   // covers weight-fill visibility too

    // ---- hoist B (weight) fragments into registers: [ks][ni][2] ----
    uint32_t rbH[4][8][2], rbL[4][8][2];
#pragma unroll
    for (int ks = 0; ks < 4; ks++) {
        const int kb = w * 64 + ks * 16;
#pragma unroll
        for (int ni = 0; ni < 8; ni++) {
            int r = ni * 8 + g;
            rbH[ks][ni][0] = *(const uint32_t*)&sWH[r * SW_K + kb + 2 * tg];
            rbH[ks][ni][1] = *(const uint32_t*)&sWH[r * SW_K + kb + 2 * tg + 8];
            rbL[ks][ni][0] = *(const uint32_t*)&sWL[r * SW_K + kb + 2 * tg];
            rbL[ks][ni][1] = *(const uint32_t*)&sWL[r * SW_K + kb + 2 * tg + 8];
        }
    }

    const int p1b = tid & 15;
    const int p1k = tid >> 4;

    const float* gxrow = gx + ((size_t)(B0 + ub) * T) * G4 + J0 + uj;
    __nv_bfloat16* hH = hsH ? hsH + ((size_t)(B0 + ub) * T) * 512 + J0 + uj : nullptr;
    __nv_bfloat16* hL = hsL ? hsL + ((size_t)(B0 + ub) * T) * 512 + J0 + uj : nullptr;

    for (int t = 0; t < T; ++t) {
        float pgi = gxrow[0], pgf = gxrow[512], pgg = gxrow[1024], pgo = gxrow[1536];

        const uint32_t* hsrc = hpub32 + (((t + 1) & 1) << 15);

        // phase 1: load packed h pairs, de-interleave hi/lo via PRMT
#pragma unroll
        for (int i = 0; i < 8; ++i) {
            int kq = p1k + (i << 4);                  // uint4 index 0..127
            uint4 hv = __ldcg((const uint4*)(hsrc + (B0 + p1b) * 512 + (kq << 2)));
            int base = p1b * SW_K + (kq << 2);
            *(uint32_t*)&sHH[base]     = __byte_perm(hv.x, hv.y, 0x5410);
            *(uint32_t*)&sHL[base]     = __byte_perm(hv.x, hv.y, 0x7632);
            *(uint32_t*)&sHH[base + 2] = __byte_perm(hv.z, hv.w, 0x5410);
            *(uint32_t*)&sHL[base + 2] = __byte_perm(hv.z, hv.w, 0x7632);
        }
        __syncthreads();

        // phase 2: HMMA m16 x n64 x k64, weights from registers
        float c[8][4];
#pragma unroll
        for (int ni = 0; ni < 8; ni++)
#pragma unroll
            for (int q = 0; q < 4; q++) c[ni][q] = 0.f;

        const int kb0 = w * 64;
#pragma unroll
        for (int ks = 0; ks < 4; ks++) {
            const int kb = kb0 + ks * 16;
            uint32_t aH[4], aL[4];
            aH[0] = *(const uint32_t*)&sHH[g * SW_K + kb + 2 * tg];
            aH[1] = *(const uint32_t*)&sHH[(g + 8) * SW_K + kb + 2 * tg];
            aH[2] = *(const uint32_t*)&sHH[g * SW_K + kb + 2 * tg + 8];
            aH[3] = *(const uint32_t*)&sHH[(g + 8) * SW_K + kb + 2 * tg + 8];
            aL[0] = *(const uint32_t*)&sHL[g * SW_K + kb + 2 * tg];
            aL[1] = *(const uint32_t*)&sHL[(g + 8) * SW_K + kb + 2 * tg];
            aL[2] = *(const uint32_t*)&sHL[g * SW_K + kb + 2 * tg + 8];
            aL[3] = *(const uint32_t*)&sHL[(g + 8) * SW_K + kb + 2 * tg + 8];
#pragma unroll
            for (int ni = 0; ni < 8; ni++) {
                mma16816(c[ni], aH, rbH[ks][ni]);
                mma16816(c[ni], aL, rbH[ks][ni]);
                mma16816(c[ni], aH, rbL[ks][ni]);
            }
        }

        // phase 3: fragments -> red[w][m][n] (pad 66)
#pragma unroll
        for (int ni = 0; ni < 8; ni++) {
            int nn = ni * 8 + 2 * tg;
            float2 v01 = make_float2(c[ni][0], c[ni][1]);
            float2 v23 = make_float2(c[ni][2], c[ni][3]);
            *(float2*)&red[w * 1056 + g * 66 + nn] = v01;
            *(float2*)&red[w * 1056 + (g + 8) * 66 + nn] = v23;
        }
        __syncthreads();

        // phase 4: reduce 8 k-slices, add gx, LSTM cell (thread = (ub,uj))
        float gsum[4];
#pragma unroll
        for (int gt = 0; gt < 4; gt++) {
            float v = 0.f;
#pragma unroll
            for (int s2 = 0; s2 < 8; s2++)
                v += red[s2 * 1056 + ub * 66 + gt * 16 + uj];
            gsum[gt] = v;
        }
        float gi = gsum[0] + pgi, gf = gsum[1] + pgf;
        float gg = gsum[2] + pgg, go = gsum[3] + pgo;

        float ig = sigf(gi), fg = sigf(gf), og_ = sigf(go), gt_ = tanhf(gg);
        cval = fg * cval + ig * gt_;
        hval = og_ * tanhf(cval);

        __nv_bfloat16 hi, lo; bf16_split(hval, hi, lo);
        uint32_t hp = (uint32_t)__bfloat16_as_ushort(hi)
                    | ((uint32_t)__bfloat16_as_ushort(lo) << 16);
        hpub32[((t & 1) << 15) + (B0 + ub) * 512 + J0 + uj] = hp;
        if (hH) { *hH = hi; *hL = lo; hH += 512; hL += 512; }
        gxrow += G4;

        ++nbar;
        group_barrier(bar, bg, nbar * 32);
    }

    hT_out[(B0 + ub) * 512 + J0 + uj] = hval;
    cT_out[(B0 + ub) * 512 + J0 + uj] = cval;
}

// ---------------- host orchestration ----------------
static __nv_bfloat16 *s_AH, *s_AL, *s_YH, *s_YL, *s_MH, *s_ML, *s_WH, *s_WL;

static void launch_mma_s(cudaStream_t st,
                         const __nv_bfloat16* AH, const __nv_bfloat16* AL,
                         const __nv_bfloat16* WHp, const __nv_bfloat16* WLp,
                         int kpad, const float* b1, const float* b2,
                         float* Cf, __nv_bfloat16* CH, __nv_bfloat16* CL,
                         int ldC, int M, int Nreal, int relu, int remapT) {
    int mt = (M + 127) / 128;
    int nt = (Nreal + 127) / 128;
    int nChunks = kpad / 32;
    mma_gemm_kernel<<<dim3(nt, mt), 256, MMA_SMEM_BYTES, st>>>(
        AH, AL, WHp, WLp, kpad, nChunks, b1, b2, Cf, CH, CL, ldC, M, Nreal, relu, remapT);
}

static void launch_convw_s(cudaStream_t st, const float* W, int N, int K, int kpad,
                           __nv_bfloat16* WHp, __nv_bfloat16* WLp) {
    int Npad = ((N + 63) / 64) * 64;
    long n = (long)Npad * kpad;
    conv_w_kernel<<<(int)((n + 255) / 256), 256, 0, st>>>(W, WHp, WLp, N, K, kpad, Npad);
}

extern "C" void kernel_launch(void* const* d_in, const int* in_sizes, int n_in,
                              void* d_out, int out_size) {
    (void)in_sizes; (void)n_in; (void)out_size;
    const float* x     = (const float*)d_in[0];
    const float* y     = (const float*)d_in[1];
    const float* eWih0 = (const float*)d_in[2];
    const float* eWhh0 = (const float*)d_in[3];
    const float* ebih0 = (const float*)d_in[4];
    const float* ebhh0 = (const float*)d_in[5];
    const float* eWih1 = (const float*)d_in[6];
    const float* eWhh1 = (const float*)d_in[7];
    const float* ebih1 = (const float*)d_in[8];
    const float* ebhh1 = (const float*)d_in[9];
    const float* dWih0 = (const float*)d_in[10];
    const float* dWhh0 = (const float*)d_in[11];
    const float* dbih0 = (const float*)d_in[12];
    const float* dbhh0 = (const float*)d_in[13];
    const float* dWih1 = (const float*)d_in[14];
    const float* dWhh1 = (const float*)d_in[15];
    const float* dbih1 = (const float*)d_in[16];
    const float* dbhh1 = (const float*)d_in[17];
    const float* clsW1 = (const float*)d_in[18];
    const float* clsb1 = (const float*)d_in[19];
    const float* clsW2 = (const float*)d_in[20];
    const float* clsb2 = (const float*)d_in[21];
    float* out = (float*)d_out;

    // stream/event statics: created on the first (uncaptured) correctness call
    static cudaStream_t sB = nullptr;
    static cudaEvent_t evFork = nullptr, evW = nullptr, evB = nullptr;
    if (sB == nullptr) {
        cudaStreamCreateWithFlags(&sB, cudaStreamNonBlocking);
        cudaEventCreateWithFlags(&evFork, cudaEventDisableTiming);
        cudaEventCreateWithFlags(&evW, cudaEventDisableTiming);
        cudaEventCreateWithFlags(&evB, cudaEventDisableTiming);
    }

    float *gx, *gx2, *hpub, *hT0, *cT0, *hT1, *cT1, *hTd, *cTd;
    unsigned* bar;
    cudaGetSymbolAddress((void**)&gx,   g_gx);
    cudaGetSymbolAddress((void**)&gx2,  g_gx2);
    cudaGetSymbolAddress((void**)&hpub, g_hpub);
    cudaGetSymbolAddress((void**)&hT0,  g_hT0);
    cudaGetSymbolAddress((void**)&cT0,  g_cT0);
    cudaGetSymbolAddress((void**)&hT1,  g_hT1);
    cudaGetSymbolAddress((void**)&cT1,  g_cT1);
    cudaGetSymbolAddress((void**)&hTd,  g_hTd);
    cudaGetSymbolAddress((void**)&cTd,  g_cTd);
    cudaGetSymbolAddress((void**)&bar,  g_bar);
    cudaGetSymbolAddress((void**)&s_AH, g_AH);
    cudaGetSymbolAddress((void**)&s_AL, g_AL);
    cudaGetSymbolAddress((void**)&s_YH, g_YH);
    cudaGetSymbolAddress((void**)&s_YL, g_YL);
    cudaGetSymbolAddress((void**)&s_MH, g_MH);
    cudaGetSymbolAddress((void**)&s_ML, g_ML);
    cudaGetSymbolAddress((void**)&s_WH, g_WHb);
    cudaGetSymbolAddress((void**)&s_WL, g_WLb);

    cudaFuncSetAttribute(lstm_scan_kernel,
                         cudaFuncAttributeMaxDynamicSharedMemorySize, SCAN_SMEM_BYTES);
    cudaFuncSetAttribute(mma_gemm_kernel,
                         cudaFuncAttributeMaxDynamicSharedMemorySize, MMA_SMEM_BYTES);

    const int ME  = MROWS_MAX;   // 65600
    const int MDN = MD_ROWS;     // 65472

    // W slots: 0=eWih0, 1=dWih0, 2=eWih1, 3=dWih1, 4=clsW1, 5=clsW2
    __nv_bfloat16 *WH0 = s_WH,             *WL0 = s_WL;
    __nv_bfloat16 *WH1 = s_WH + 1 * WSLOT, *WL1 = s_WL + 1 * WSLOT;
    __nv_bfloat16 *WH2 = s_WH + 2 * WSLOT, *WL2 = s_WL + 2 * WSLOT;
    __nv_bfloat16 *WH3 = s_WH + 3 * WSLOT, *WL3 = s_WL + 3 * WSLOT;
    __nv_bfloat16 *WH4 = s_WH + 4 * WSLOT, *WL4 = s_WL + 4 * WSLOT;
    __nv_bfloat16 *WH5 = s_WH + 5 * WSLOT, *WL5 = s_WL + 5 * WSLOT;

    // -------- stream A: barrier reset (all 16 slots, once) + encoder L0 -----
    reset_bar_kernel<<<1, 32>>>(bar);
    {
        long n = (long)BATCH * T_ENC * 192;
        pad_shift_bf16_kernel<<<(int)((n + 255) / 256), 256>>>(x, s_AH, s_AL, 1024, T_ENC, 1024);
    }
    launch_convw_s(0, eWih0, G4, DIN, 192, WH0, WL0);
    launch_mma_s(0, s_AH, s_AL, WH0, WL0, 192, ebih0, ebhh0,
                 gx, nullptr, nullptr, G4, ME, G4, 0, 0);
    cudaEventRecord(evFork, 0);

    // -------- stream B (overlapped with encoder scans) --------
    cudaStreamWaitEvent(sB, evFork, 0);
    zero_t0_kernel<<<(BATCH * DIN + 255) / 256, 256, 0, sB>>>(out);
    {
        long n = (long)BATCH * T_DEC * 192;
        pad_shift_bf16_kernel<<<(int)((n + 255) / 256), 256, 0, sB>>>(y, s_YH, s_YL, 1024, T_DEC, 1022);
    }
    launch_convw_s(sB, dWih0, G4, DIN, 192, WH1, WL1);
    launch_convw_s(sB, eWih1, G4, HID, 512, WH2, WL2);
    launch_convw_s(sB, dWih1, G4, HID, 512, WH3, WL3);
    launch_convw_s(sB, clsW1, 256, HID, 512, WH4, WL4);
    launch_convw_s(sB, clsW2, DIN, 256, 256, WH5, WL5);
    cudaEventRecord(evW, sB);
    launch_mma_s(sB, s_YH, s_YL, WH1, WL1, 192, dbih0, dbhh0,
                 gx2, nullptr, nullptr, G4, MDN, G4, 0, 0);
    cudaEventRecord(evB, sB);

    // -------- stream A continues: encoder scans --------
    lstm_scan_kernel<<<128, 256, SCAN_SMEM_BYTES>>>(gx, eWhh0, nullptr, nullptr,
                                                    s_AH, s_AL, hT0, cT0, hpub, bar + 0, T_ENC);
    cudaStreamWaitEvent(0, evW, 0);
    launch_mma_s(0, s_AH, s_AL, WH2, WL2, 512, ebih1, ebhh1,
                 gx, nullptr, nullptr, G4, ME, G4, 0, 0);
    lstm_scan_kernel<<<128, 256, SCAN_SMEM_BYTES>>>(gx, eWhh1, nullptr, nullptr,
                                                    nullptr, nullptr, hT1, cT1, hpub, bar + 4, T_ENC);

    // -------- decoder --------
    cudaStreamWaitEvent(0, evB, 0);
    lstm_scan_kernel<<<128, 256, SCAN_SMEM_BYTES>>>(gx2, dWhh0, hT0, cT0,
                                                    s_AH, s_AL, hTd, cTd, hpub, bar + 8, T_DEC);
    launch_mma_s(0, s_AH, s_AL, WH3, WL3, 512, dbih1, dbhh1,
                 gx, nullptr, nullptr, G4, MDN, G4, 0, 0);
    lstm_scan_kernel<<<128, 256, SCAN_SMEM_BYTES>>>(gx, dWhh1, hT1, cT1,
                                                    s_AH, s_AL, hTd, cTd, hpub, bar + 12, T_DEC);

    // -------- classifier --------
    launch_mma_s(0, s_AH, s_AL, WH4, WL4, 512, clsb1, nullptr,
                 nullptr, s_MH, s_ML, 256, MDN, 256, 1, 0);
    launch_mma_s(0, s_MH, s_ML, WH5, WL5, 256, clsb2, nullptr,
                 out, nullptr, nullptr, DIN, MDN, DIN, 0, T_DEC);
}

// round 15
// speedup vs baseline: 1.0449x; 1.0072x over previous
#include <cuda_runtime.h>
#include <cuda_bf16.h>
#include <cstdint>

typedef unsigned long long ull;

// ---------------- problem constants ----------------
#define BATCH 64
#define DIN   176
#define HID   512
#define G4    2048          // 4*HID
#define T_ENC 1025          // 1 + 1024
#define T_DEC 1023          // TTGT - 1
#define MROWS_MAX (BATCH * T_ENC)   // 65600
#define MD_ROWS   (BATCH * T_DEC)   // 65472

// ---------------- scratch (static device globals; no cudaMalloc allowed) ----
__device__ float g_gx [(size_t)MROWS_MAX * G4];    // gx buffer (stream A)
__device__ float g_gx2[(size_t)MROWS_MAX * G4];    // gx buffer (overlapped dec L0)
#define ABUF_ROWS (MROWS_MAX + 128)
__device__ __nv_bfloat16 g_AH[(size_t)ABUF_ROWS * 512];   // A operand hi
__device__ __nv_bfloat16 g_AL[(size_t)ABUF_ROWS * 512];   // A operand lo
#define YBUF_ROWS (MD_ROWS + 128)
__device__ __nv_bfloat16 g_YH[(size_t)YBUF_ROWS * 192];   // dec input hi
__device__ __nv_bfloat16 g_YL[(size_t)YBUF_ROWS * 192];   // dec input lo
#define MBUF_ROWS (MD_ROWS + 128)
__device__ __nv_bfloat16 g_MH[(size_t)MBUF_ROWS * 256];   // hmid hi
__device__ __nv_bfloat16 g_ML[(size_t)MBUF_ROWS * 256];   // hmid lo
#define WSLOT (2048 * 512)
__device__ __nv_bfloat16 g_WHb[6 * WSLOT];                // W hi, 6 slots
__device__ __nv_bfloat16 g_WLb[6 * WSLOT];                // W lo, 6 slots
__device__ float g_hpub[2 * BATCH * HID];                 // packed (hi,lo) bf16 pairs
__device__ float g_hT0[BATCH * HID], g_cT0[BATCH * HID];
__device__ float g_hT1[BATCH * HID], g_cT1[BATCH * HID];
__device__ float g_hTd[BATCH * HID], g_cTd[BATCH * HID];
__device__ unsigned g_bar[16];                            // 4 slots x 4 scans

// ---------------- helpers ----------------
__device__ __forceinline__ void bf16_split(float v, __nv_bfloat16& hi, __nv_bfloat16& lo) {
    hi = __float2bfloat16(v);
    lo = __float2bfloat16(v - __bfloat162float(hi));
}

__device__ __forceinline__ uint32_t smem_to_u32(const void* p) {
    uint32_t a;
    asm("{ .reg .u64 t; cvta.to.shared.u64 t, %1; cvt.u32.u64 %0, t; }" : "=r"(a) : "l"(p));
    return a;
}

// HMMA m16n8k16 bf16 (non-arch-gated PTX; runs on sm_103 base target)
__device__ __forceinline__ void mma16816(float* d, const uint32_t* a, const uint32_t* b) {
    asm volatile(
        "mma.sync.aligned.m16n8k16.row.col.f32.bf16.bf16.f32 "
        "{%0,%1,%2,%3}, {%4,%5,%6,%7}, {%8,%9}, {%0,%1,%2,%3};"
        : "+f"(d[0]), "+f"(d[1]), "+f"(d[2]), "+f"(d[3])
        : "r"(a[0]), "r"(a[1]), "r"(a[2]), "r"(a[3]), "r"(b[0]), "r"(b[1]));
}

// ldmatrix x4 (sm_75 PTX, non-gated)
__device__ __forceinline__ void ldsm4(uint32_t* r, uint32_t addr) {
    asm volatile("ldmatrix.sync.aligned.m8n8.x4.shared.b16 {%0,%1,%2,%3}, [%4];"
        : "=r"(r[0]), "=r"(r[1]), "=r"(r[2]), "=r"(r[3]) : "r"(addr));
}

// cp.async 16B (LDGSTS; sm_80 PTX, non-gated)
__device__ __forceinline__ void cpasync16(uint32_t s, const void* g) {
    asm volatile("cp.async.cg.shared.global [%0], [%1], 16;" :: "r"(s), "l"(g));
}
#define CP_COMMIT() asm volatile("cp.async.commit_group;" ::: "memory")
#define CP_WAIT1()  asm volatile("cp.async.wait_group 1;" ::: "memory")

// ---------------- small utility kernels ----------------
__global__ void reset_bar_kernel(unsigned* bar) {
    if (threadIdx.x < 16) bar[threadIdx.x] = 0u;
}

// padded-shifted input -> bf16 hi/lo, layout [b][t][192] (cols 176..191 zero)
__global__ void pad_shift_bf16_kernel(const float* __restrict__ src,
                                      __nv_bfloat16* __restrict__ dH,
                                      __nv_bfloat16* __restrict__ dL,
                                      int Tsrc, int Tpad, int Tcopy) {
    long n = (long)BATCH * Tpad * 192;
    long i = (long)blockIdx.x * blockDim.x + threadIdx.x;
    if (i >= n) return;
    int d = (int)(i % 192);
    long bt = i / 192;
    int t = (int)(bt % Tpad);
    int b = (int)(bt / Tpad);
    float v = (d < DIN && t > 0 && t <= Tcopy) ? src[((long)b * Tsrc + (t - 1)) * DIN + d] : 0.f;
    __nv_bfloat16 hi, lo; bf16_split(v, hi, lo);
    dH[i] = hi; dL[i] = lo;
}

// W (N x K fp32) -> WH/WL (Npad x kpad bf16, zero padded)
__global__ void conv_w_kernel(const float* __restrict__ W,
                              __nv_bfloat16* __restrict__ WH, __nv_bfloat16* __restrict__ WL,
                              int N, int K, int kpad, int Npad) {
    long n = (long)Npad * kpad;
    long i = (long)blockIdx.x * blockDim.x + threadIdx.x;
    if (i >= n) return;
    int row = (int)(i / kpad), c = (int)(i % kpad);
    float v = (row < N && c < K) ? W[(size_t)row * K + c] : 0.f;
    __nv_bfloat16 hi, lo; bf16_split(v, hi, lo);
    WH[i] = hi; WL[i] = lo;
}

__global__ void zero_t0_kernel(float* __restrict__ out) {
    int i = blockIdx.x * blockDim.x + threadIdx.x;
    if (i < BATCH * DIN) {
        int b = i / DIN, d = i % DIN;
        out[(size_t)b * 1024 * DIN + d] = 0.f;
    }
}

// ---------------- HMMA GEMM (128x128 tile, cp.async 2-stage, ldmatrix) -----
#define SOFF_AL  5120
#define SOFF_BH  10240
#define SOFF_BL  15360
#define STG_ELEMS 20480
#define MMA_SMEM_BYTES (2 * STG_ELEMS * 2)   // 81920

__global__ void __launch_bounds__(256, 2)
mma_gemm_kernel(const __nv_bfloat16* __restrict__ AH, const __nv_bfloat16* __restrict__ AL,
                const __nv_bfloat16* __restrict__ WH, const __nv_bfloat16* __restrict__ WL,
                int kpad, int nChunks,
                const float* __restrict__ b1, const float* __restrict__ b2,
                float* __restrict__ Cf, __nv_bfloat16* __restrict__ CH,
                __nv_bfloat16* __restrict__ CL,
                int ldC, int M, int Nreal, int relu, int remapT) {
    extern __shared__ __align__(16) __nv_bfloat16 smbuf[];
    const uint32_t sb = smem_to_u32(smbuf);

    const int tid  = threadIdx.x;
    const int wid  = tid >> 5, lane = tid & 31;
    const int g    = lane >> 2, tg = lane & 3;
    const int m0   = (wid & 3) * 32;
    const int n0   = (wid >> 2) * 64;
    const int row0 = blockIdx.y * 128;
    const int col0 = blockIdx.x * 128;

    const int lr0 = tid >> 2, lseg = tid & 3;   // loader: rows lr0, lr0+64

    // ldmatrix per-lane element offsets (element units, exclude kb and region)
    const int aoff = (m0 + (lane & 15)) * 40 + ((lane >> 4) << 3);
    const int boff = (n0 + ((lane & 7) + ((lane >> 4) << 3))) * 40
                   + (((lane >> 3) & 1) << 3);

    float d[2][8][4];
#pragma unroll
    for (int mi = 0; mi < 2; mi++)
#pragma unroll
        for (int ni = 0; ni < 8; ni++)
#pragma unroll
            for (int q = 0; q < 4; q++) d[mi][ni][q] = 0.f;

    auto load_chunk = [&](int ch, int stg) {
        const int kbase = ch * 32;
        const uint32_t base = sb + stg * (STG_ELEMS * 2);
#pragma unroll
        for (int i = 0; i < 2; i++) {
            int r = lr0 + i * 64;
            size_t ga = (size_t)(row0 + r) * kpad + kbase + lseg * 8;
            size_t gb = (size_t)(col0 + r) * kpad + kbase + lseg * 8;
            uint32_t so = base + (r * 40 + lseg * 8) * 2;
            cpasync16(so, AH + ga);
            cpasync16(so + SOFF_AL * 2, AL + ga);
            cpasync16(so + SOFF_BH * 2, WH + gb);
            cpasync16(so + SOFF_BL * 2, WL + gb);
        }
    };

    load_chunk(0, 0);
    CP_COMMIT();

    for (int ch = 0; ch < nChunks; ch++) {
        const int cur = ch & 1;
        if (ch + 1 < nChunks) load_chunk(ch + 1, cur ^ 1);
        CP_COMMIT();
        CP_WAIT1();
        __syncthreads();

        const uint32_t bufb = sb + cur * (STG_ELEMS * 2);

#pragma unroll
        for (int ks = 0; ks < 2; ks++) {
            const int kb = ks * 16;
            uint32_t aH[2][4], aL[2][4];
#pragma unroll
            for (int mi = 0; mi < 2; mi++) {
                uint32_t ad = bufb + (uint32_t)(aoff + mi * 16 * 40 + kb) * 2;
                ldsm4(aH[mi], ad);
                ldsm4(aL[mi], ad + SOFF_AL * 2);
            }
            uint32_t bH[8][2], bL[8][2];
#pragma unroll
            for (int p = 0; p < 4; p++) {
                uint32_t bd = bufb + SOFF_BH * 2 + (uint32_t)(boff + p * 16 * 40 + kb) * 2;
                uint32_t rH[4], rL[4];
                ldsm4(rH, bd);
                ldsm4(rL, bd + (SOFF_BL - SOFF_BH) * 2);
                bH[2 * p][0] = rH[0]; bH[2 * p][1] = rH[1];
                bH[2 * p + 1][0] = rH[2]; bH[2 * p + 1][1] = rH[3];
                bL[2 * p][0] = rL[0]; bL[2 * p][1] = rL[1];
                bL[2 * p + 1][0] = rL[2]; bL[2 * p + 1][1] = rL[3];
            }
#pragma unroll
            for (int ni = 0; ni < 8; ni++) {
#pragma unroll
                for (int mi = 0; mi < 2; mi++) {
                    mma16816(d[mi][ni], aH[mi], bH[ni]);
                    mma16816(d[mi][ni], aL[mi], bH[ni]);
                    mma16816(d[mi][ni], aH[mi], bL[ni]);
                }
            }
        }
        __syncthreads();
    }

    // epilogue: bias/relu, optional remap, fp32 and/or bf16 hi/lo stores
#pragma unroll
    for (int mi = 0; mi < 2; mi++) {
#pragma unroll
        for (int rr = 0; rr < 2; rr++) {
            int r = row0 + m0 + mi * 16 + g + rr * 8;
            if (r >= M) continue;
            size_t rowbase;
            if (remapT > 0) {
                int bb = r / remapT, tt = r - bb * remapT;
                rowbase = ((size_t)bb * (remapT + 1) + tt + 1) * (size_t)ldC;
            } else {
                rowbase = (size_t)r * ldC;
            }
#pragma unroll
            for (int ni = 0; ni < 8; ni++) {
#pragma unroll
                for (int cc = 0; cc < 2; cc++) {
                    int col = col0 + n0 + ni * 8 + 2 * tg + cc;
                    if (col >= Nreal) continue;
                    float v = d[mi][ni][rr * 2 + cc]
                            + (b1 ? __ldg(b1 + col) : 0.f) + (b2 ? __ldg(b2 + col) : 0.f);
                    if (relu) v = fmaxf(v, 0.f);
                    if (Cf) Cf[rowbase + col] = v;
                    if (CH) {
                        __nv_bfloat16 hi, lo; bf16_split(v, hi, lo);
                        CH[rowbase + col] = hi;
                        CL[rowbase + col] = lo;
                    }
                }
            }
        }
    }
}

// ---------------- persistent LSTM scan (round-14, unchanged) ---------------
#define SW_K     520
#define SOFF_WL2 (64 * SW_K)               // 33280
#define SOFF_HH  (2 * 64 * SW_K)           // 66560
#define SOFF_HL  (SOFF_HH + 16 * SW_K)     // 74880
#define SCAN_BF16_ELEMS (SOFF_HL + 16 * SW_K)   // 83200
#define SCAN_RED_FLOATS (8 * 16 * 66)      // 8448
#define SCAN_SMEM_BYTES (SCAN_BF16_ELEMS * 2 + SCAN_RED_FLOATS * 4)  // 200192

__device__ __forceinline__ float sigf(float x) { return 1.f / (1.f + expf(-x)); }

__device__ __forceinline__ void group_barrier(unsigned* bar, int bg, unsigned target) {
    __threadfence();
    __syncthreads();
    if (threadIdx.x == 0) {
        atomicAdd(&bar[bg], 1u);
        while (atomicAdd(&bar[bg], 0u) < target) { __nanosleep(64); }
        __threadfence();
    }
    __syncthreads();
}

__global__ void __launch_bounds__(256, 1)
lstm_scan_kernel(const float* __restrict__ gx, const float* __restrict__ Whh,
                 const float* __restrict__ h0, const float* __restrict__ c0,
                 __nv_bfloat16* __restrict__ hsH, __nv_bfloat16* __restrict__ hsL,
                 float* __restrict__ hT_out, float* __restrict__ cT_out,
                 float* __restrict__ hpub, unsigned* __restrict__ bar, int T) {
    extern __shared__ __align__(16) __nv_bfloat16 sm[];
    __nv_bfloat16* sWH = sm;                 // [64][520] (used once)
    __nv_bfloat16* sWL = sm + SOFF_WL2;      // [64][520] (used once)
    __nv_bfloat16* sHH = sm + SOFF_HH;       // [16][520]
    __nv_bfloat16* sHL = sm + SOFF_HL;       // [16][520]
    float* red = (float*)(sm + SCAN_BF16_ELEMS);  // [8][16][66]

    uint32_t* hpub32 = (uint32_t*)hpub;      // packed (hi | lo<<16) bf16 pairs

    const int tid = threadIdx.x;
    const int bg = blockIdx.x >> 5;
    const int ht = blockIdx.x & 31;
    const int B0 = bg * 16;
    const int J0 = ht * 16;
    const int w = tid >> 5;
    const int lane = tid & 31;
    const int g = lane >> 2, tg = lane & 3;

    // ---- load + split Whh slice into smem (once); n = gate*16 + j ----
    for (int idx = tid; idx < 64 * 512; idx += 256) {
        int n = idx >> 9, k = idx & 511;
        float v = Whh[(size_t)((n >> 4) * 512 + J0 + (n & 15)) * 512 + k];
        __nv_bfloat16 hi, lo; bf16_split(v, hi, lo);
        sWH[n * SW_K + k] = hi;
        sWL[n * SW_K + k] = lo;
    }

    // ---- init states ----
    const int ub = tid >> 4;            // batch within tile (0..15)
    const int uj = tid & 15;            // hidden within tile (0..15)
    float cval = c0 ? c0[(B0 + ub) * 512 + J0 + uj] : 0.f;
    float hval = h0 ? h0[(B0 + ub) * 512 + J0 + uj] : 0.f;
    {
        __nv_bfloat16 hi, lo; bf16_split(hval, hi, lo);
        uint32_t hp = (uint32_t)__bfloat16_as_ushort(hi)
                    | ((uint32_t)__bfloat16_as_ushort(lo) << 16);
        hpub32[32768 + (B0 + ub) * 512 + J0 + uj] = hp;   // parity-1 feeds t=0
    }

    unsigned nbar = 1;
    group_barrier(bar, bg, nbar * 32);   // covers weight-fill visibility too

    // ---- hoist B (weight) fragments into registers: [ks][ni][2] ----
    uint32_t rbH[4][8][2], rbL[4][8][2];
#pragma unroll
    for (int ks = 0; ks < 4; ks++) {
        const int kb = w * 64 + ks * 16;
#pragma unroll
        for (int ni = 0; ni < 8; ni++) {
            int r = ni * 8 + g;
            rbH[ks][ni][0] = *(const uint32_t*)&sWH[r * SW_K + kb + 2 * tg];
            rbH[ks][ni][1] = *(const uint32_t*)&sWH[r * SW_K + kb + 2 * tg + 8];
            rbL[ks][ni][0] = *(const uint32_t*)&sWL[r * SW_K + kb + 2 * tg];
            rbL[ks][ni][1] = *(const uint32_t*)&sWL[r * SW_K + kb + 2 * tg + 8];
        }
    }

    const int p1b = tid & 15;
    const int p1k = tid >> 4;

    const float* gxrow = gx + ((size_t)(B0 + ub) * T) * G4 + J0 + uj;
    __nv_bfloat16* hH = hsH ? hsH + ((size_t)(B0 + ub) * T) * 512 + J0 + uj : nullptr;
    __nv_bfloat16* hL = hsL ? hsL + ((size_t)(B0 + ub) * T) * 512 + J0 + uj : nullptr;

    for (int t = 0; t < T; ++t) {
        float pgi = gxrow[0], pgf = gxrow[512], pgg = gxrow[1024], pgo = gxrow[1536];

        const uint32_t* hsrc = hpub32 + (((t + 1) & 1) << 15);

        // phase 1: load packed h pairs, de-interleave hi/lo via PRMT
#pragma unroll
        for (int i = 0; i < 8; ++i) {
            int kq = p1k + (i << 4);                  // uint4 index 0..127
            uint4 hv = __ldcg((const uint4*)(hsrc + (B0 + p1b) * 512 + (kq << 2)));
            int base = p1b * SW_K + (kq << 2);
            *(uint32_t*)&sHH[base]     = __byte_perm(hv.x, hv.y, 0x5410);
            *(uint32_t*)&sHL[base]     = __byte_perm(hv.x, hv.y, 0x7632);
            *(uint32_t*)&sHH[base + 2] = __byte_perm(hv.z, hv.w, 0x5410);
            *(uint32_t*)&sHL[base + 2] = __byte_perm(hv.z, hv.w, 0x7632);
        }
        __syncthreads();

        // phase 2: HMMA m16 x n64 x k64, weights from registers
        float c[8][4];
#pragma unroll
        for (int ni = 0; ni < 8; ni++)
#pragma unroll
            for (int q = 0; q < 4; q++) c[ni][q] = 0.f;

        const int kb0 = w * 64;
#pragma unroll
        for (int ks = 0; ks < 4; ks++) {
            const int kb = kb0 + ks * 16;
            uint32_t aH[4], aL[4];
            aH[0] = *(const uint32_t*)&sHH[g * SW_K + kb + 2 * tg];
            aH[1] = *(const uint32_t*)&sHH[(g + 8) * SW_K + kb + 2 * tg];
            aH[2] = *(const uint32_t*)&sHH[g * SW_K + kb + 2 * tg + 8];
            aH[3] = *(const uint32_t*)&sHH[(g + 8) * SW_K + kb + 2 * tg + 8];
            aL[0] = *(const uint32_t*)&sHL[g * SW_K + kb + 2 * tg];
            aL[1] = *(const uint32_t*)&sHL[(g + 8) * SW_K + kb + 2 * tg];
            aL[2] = *(const uint32_t*)&sHL[g * SW_K + kb + 2 * tg + 8];
            aL[3] = *(const uint32_t*)&sHL[(g + 8) * SW_K + kb + 2 * tg + 8];
#pragma unroll
            for (int ni = 0; ni < 8; ni++) {
                mma16816(c[ni], aH, rbH[ks][ni]);
                mma16816(c[ni], aL, rbH[ks][ni]);
                mma16816(c[ni], aH, rbL[ks][ni]);
            }
        }

        // phase 3: fragments -> red[w][m][n] (pad 66)
#pragma unroll
        for (int ni = 0; ni < 8; ni++) {
            int nn = ni * 8 + 2 * tg;
            float2 v01 = make_float2(c[ni][0], c[ni][1]);
            float2 v23 = make_float2(c[ni][2], c[ni][3]);
            *(float2*)&red[w * 1056 + g * 66 + nn] = v01;
            *(float2*)&red[w * 1056 + (g + 8) * 66 + nn] = v23;
        }
        __syncthreads();

        // phase 4: reduce 8 k-slices, add gx, LSTM cell (thread = (ub,uj))
        float gsum[4];
#pragma unroll
        for (int gt = 0; gt < 4; gt++) {
            float v = 0.f;
#pragma unroll
            for (int s2 = 0; s2 < 8; s2++)
                v += red[s2 * 1056 + ub * 66 + gt * 16 + uj];
            gsum[gt] = v;
        }
        float gi = gsum[0] + pgi, gf = gsum[1] + pgf;
        float gg = gsum[2] + pgg, go = gsum[3] + pgo;

        float ig = sigf(gi), fg = sigf(gf), og_ = sigf(go), gt_ = tanhf(gg);
        cval = fg * cval + ig * gt_;
        hval = og_ * tanhf(cval);

        __nv_bfloat16 hi, lo; bf16_split(hval, hi, lo);
        uint32_t hp = (uint32_t)__bfloat16_as_ushort(hi)
                    | ((uint32_t)__bfloat16_as_ushort(lo) << 16);
        hpub32[((t & 1) << 15) + (B0 + ub) * 512 + J0 + uj] = hp;
        if (hH) { *hH = hi; *hL = lo; hH += 512; hL += 512; }
        gxrow += G4;

        ++nbar;
        group_barrier(bar, bg, nbar * 32);
    }

    hT_out[(B0 + ub) * 512 + J0 + uj] = hval;
    cT_out[(B0 + ub) * 512 + J0 + uj] = cval;
}

// ---------------- host orchestration ----------------
static __nv_bfloat16 *s_AH, *s_AL, *s_YH, *s_YL, *s_MH, *s_ML, *s_WH, *s_WL;

static void launch_mma_s(cudaStream_t st,
                         const __nv_bfloat16* AH, const __nv_bfloat16* AL,
                         const __nv_bfloat16* WHp, const __nv_bfloat16* WLp,
                         int kpad, const float* b1, const float* b2,
                         float* Cf, __nv_bfloat16* CH, __nv_bfloat16* CL,
                         int ldC, int M, int Nreal, int relu, int remapT) {
    int mt = (M + 127) / 128;
    int nt = (Nreal + 127) / 128;
    int nChunks = kpad / 32;
    mma_gemm_kernel<<<dim3(nt, mt), 256, MMA_SMEM_BYTES, st>>>(
        AH, AL, WHp, WLp, kpad, nChunks, b1, b2, Cf, CH, CL, ldC, M, Nreal, relu, remapT);
}

static void launch_convw_s(cudaStream_t st, const float* W, int N, int K, int kpad,
                           __nv_bfloat16* WHp, __nv_bfloat16* WLp) {
    int Npad = ((N + 63) / 64) * 64;
    long n = (long)Npad * kpad;
    conv_w_kernel<<<(int)((n + 255) / 256), 256, 0, st>>>(W, WHp, WLp, N, K, kpad, Npad);
}

extern "C" void kernel_launch(void* const* d_in, const int* in_sizes, int n_in,
                              void* d_out, int out_size) {
    (void)in_sizes; (void)n_in; (void)out_size;
    const float* x     = (const float*)d_in[0];
    const float* y     = (const float*)d_in[1];
    const float* eWih0 = (const float*)d_in[2];
    const float* eWhh0 = (const float*)d_in[3];
    const float* ebih0 = (const float*)d_in[4];
    const float* ebhh0 = (const float*)d_in[5];
    const float* eWih1 = (const float*)d_in[6];
    const float* eWhh1 = (const float*)d_in[7];
    const float* ebih1 = (const float*)d_in[8];
    const float* ebhh1 = (const float*)d_in[9];
    const float* dWih0 = (const float*)d_in[10];
    const float* dWhh0 = (const float*)d_in[11];
    const float* dbih0 = (const float*)d_in[12];
    const float* dbhh0 = (const float*)d_in[13];
    const float* dWih1 = (const float*)d_in[14];
    const float* dWhh1 = (const float*)d_in[15];
    const float* dbih1 = (const float*)d_in[16];
    const float* dbhh1 = (const float*)d_in[17];
    const float* clsW1 = (const float*)d_in[18];
    const float* clsb1 = (const float*)d_in[19];
    const float* clsW2 = (const float*)d_in[20];
    const float* clsb2 = (const float*)d_in[21];
    float* out = (float*)d_out;

    // stream/event statics: created on the first (uncaptured) correctness call
    static cudaStream_t sB = nullptr;
    static cudaEvent_t evFork = nullptr, evW = nullptr, evB = nullptr;
    if (sB == nullptr) {
        cudaStreamCreateWithFlags(&sB, cudaStreamNonBlocking);
        cudaEventCreateWithFlags(&evFork, cudaEventDisableTiming);
        cudaEventCreateWithFlags(&evW, cudaEventDisableTiming);
        cudaEventCreateWithFlags(&evB, cudaEventDisableTiming);
    }

    float *gx, *gx2, *hpub, *hT0, *cT0, *hT1, *cT1, *hTd, *cTd;
    unsigned* bar;
    cudaGetSymbolAddress((void**)&gx,   g_gx);
    cudaGetSymbolAddress((void**)&gx2,  g_gx2);
    cudaGetSymbolAddress((void**)&hpub, g_hpub);
    cudaGetSymbolAddress((void**)&hT0,  g_hT0);
    cudaGetSymbolAddress((void**)&cT0,  g_cT0);
    cudaGetSymbolAddress((void**)&hT1,  g_hT1);
    cudaGetSymbolAddress((void**)&cT1,  g_cT1);
    cudaGetSymbolAddress((void**)&hTd,  g_hTd);
    cudaGetSymbolAddress((void**)&cTd,  g_cTd);
    cudaGetSymbolAddress((void**)&bar,  g_bar);
    cudaGetSymbolAddress((void**)&s_AH, g_AH);
    cudaGetSymbolAddress((void**)&s_AL, g_AL);
    cudaGetSymbolAddress((void**)&s_YH, g_YH);
    cudaGetSymbolAddress((void**)&s_YL, g_YL);
    cudaGetSymbolAddress((void**)&s_MH, g_MH);
    cudaGetSymbolAddress((void**)&s_ML, g_ML);
    cudaGetSymbolAddress((void**)&s_WH, g_WHb);
    cudaGetSymbolAddress((void**)&s_WL, g_WLb);

    cudaFuncSetAttribute(lstm_scan_kernel,
                         cudaFuncAttributeMaxDynamicSharedMemorySize, SCAN_SMEM_BYTES);
    cudaFuncSetAttribute(mma_gemm_kernel,
                         cudaFuncAttributeMaxDynamicSharedMemorySize, MMA_SMEM_BYTES);

    const int ME  = MROWS_MAX;   // 65600
    const int MDN = MD_ROWS;     // 65472

    // W slots: 0=eWih0, 1=dWih0, 2=eWih1, 3=dWih1, 4=clsW1, 5=clsW2
    __nv_bfloat16 *WH0 = s_WH,             *WL0 = s_WL;
    __nv_bfloat16 *WH1 = s_WH + 1 * WSLOT, *WL1 = s_WL + 1 * WSLOT;
    __nv_bfloat16 *WH2 = s_WH + 2 * WSLOT, *WL2 = s_WL + 2 * WSLOT;
    __nv_bfloat16 *WH3 = s_WH + 3 * WSLOT, *WL3 = s_WL + 3 * WSLOT;
    __nv_bfloat16 *WH4 = s_WH + 4 * WSLOT, *WL4 = s_WL + 4 * WSLOT;
    __nv_bfloat16 *WH5 = s_WH + 5 * WSLOT, *WL5 = s_WL + 5 * WSLOT;

    // -------- stream A: barrier reset (all 16 slots, once) + encoder L0 -----
    reset_bar_kernel<<<1, 32>>>(bar);
    {
        long n = (long)BATCH * T_ENC * 192;
        pad_shift_bf16_kernel<<<(int)((n + 255) / 256), 256>>>(x, s_AH, s_AL, 1024, T_ENC, 1024);
    }
    launch_convw_s(0, eWih0, G4, DIN, 192, WH0, WL0);
    launch_mma_s(0, s_AH, s_AL, WH0, WL0, 192, ebih0, ebhh0,
                 gx, nullptr, nullptr, G4, ME, G4, 0, 0);
    cudaEventRecord(evFork, 0);

    // -------- stream B (overlapped with encoder scans) --------
    cudaStreamWaitEvent(sB, evFork, 0);
    zero_t0_kernel<<<(BATCH * DIN + 255) / 256, 256, 0, sB>>>(out);
    {
        long n = (long)BATCH * T_DEC * 192;
        pad_shift_bf16_kernel<<<(int)((n + 255) / 256), 256, 0, sB>>>(y, s_YH, s_YL, 1024, T_DEC, 1022);
    }
    launch_convw_s(sB, dWih0, G4, DIN, 192, WH1, WL1);
    launch_convw_s(sB, eWih1, G4, HID, 512, WH2, WL2);
    launch_convw_s(sB, dWih1, G4, HID, 512, WH3, WL3);
    launch_convw_s(sB, clsW1, 256, HID, 512, WH4, WL4);
    launch_convw_s(sB, clsW2, DIN, 256, 256, WH5, WL5);
    cudaEventRecord(evW, sB);
    launch_mma_s(sB, s_YH, s_YL, WH1, WL1, 192, dbih0, dbhh0,
                 gx2, nullptr, nullptr, G4, MDN, G4, 0, 0);
    cudaEventRecord(evB, sB);

    // -------- stream A continues: encoder scans --------
    lstm_scan_kernel<<<128, 256, SCAN_SMEM_BYTES>>>(gx, eWhh0, nullptr, nullptr,
                                                    s_AH, s_AL, hT0, cT0, hpub, bar + 0, T_ENC);
    cudaStreamWaitEvent(0, evW, 0);
    launch_mma_s(0, s_AH, s_AL, WH2, WL2, 512, ebih1, ebhh1,
                 gx, nullptr, nullptr, G4, ME, G4, 0, 0);
    lstm_scan_kernel<<<128, 256, SCAN_SMEM_BYTES>>>(gx, eWhh1, nullptr, nullptr,
                                                    nullptr, nullptr, hT1, cT1, hpub, bar + 4, T_ENC);

    // -------- decoder --------
    cudaStreamWaitEvent(0, evB, 0);
    lstm_scan_kernel<<<128, 256, SCAN_SMEM_BYTES>>>(gx2, dWhh0, hT0, cT0,
                                                    s_AH, s_AL, hTd, cTd, hpub, bar + 8, T_DEC);
    launch_mma_s(0, s_AH, s_AL, WH3, WL3, 512, dbih1, dbhh1,
                 gx, nullptr, nullptr, G4, MDN, G4, 0, 0);
    lstm_scan_kernel<<<128, 256, SCAN_SMEM_BYTES>>>(gx, dWhh1, hT1, cT1,
                                                    s_AH, s_AL, hTd, cTd, hpub, bar + 12, T_DEC);

    // -------- classifier --------
    launch_mma_s(0, s_AH, s_AL, WH4, WL4, 512, clsb1, nullptr,
                 nullptr, s_MH, s_ML, 256, MDN, 256, 1, 0);
    launch_mma_s(0, s_MH, s_ML, WH5, WL5, 256, clsb2, nullptr,
                 out, nullptr, nullptr, DIN, MDN, DIN, 0, T_DEC);
}

// round 16
// speedup vs baseline: 1.0658x; 1.0200x over previous
#include <cuda_runtime.h>
#include <cuda_bf16.h>
#include <cstdint>

typedef unsigned long long ull;

// ---------------- problem constants ----------------
#define BATCH 64
#define DIN   176
#define HID   512
#define G4    2048          // 4*HID
#define T_ENC 1025          // 1 + 1024
#define T_DEC 1023          // TTGT - 1
#define MROWS_MAX (BATCH * T_ENC)   // 65600
#define MD_ROWS   (BATCH * T_DEC)   // 65472

// ---------------- scratch (static device globals; no cudaMalloc allowed) ----
__device__ float g_gx [(size_t)MROWS_MAX * G4];    // gx buffer (encoder layers)
__device__ float g_gx2[(size_t)MROWS_MAX * G4];    // gx buffer (decoder layers)
#define ABUF_ROWS (MROWS_MAX + 128)
__device__ __nv_bfloat16 g_AH[(size_t)ABUF_ROWS * 512];   // enc seq / dec L1 out hi
__device__ __nv_bfloat16 g_AL[(size_t)ABUF_ROWS * 512];   // enc seq / dec L1 out lo
__device__ __nv_bfloat16 g_BH[(size_t)ABUF_ROWS * 512];   // dec L0 out hi
__device__ __nv_bfloat16 g_BL[(size_t)ABUF_ROWS * 512];   // dec L0 out lo
#define YBUF_ROWS (MD_ROWS + 128)
__device__ __nv_bfloat16 g_YH[(size_t)YBUF_ROWS * 192];   // dec input hi
__device__ __nv_bfloat16 g_YL[(size_t)YBUF_ROWS * 192];   // dec input lo
#define MBUF_ROWS (MD_ROWS + 128)
__device__ __nv_bfloat16 g_MH[(size_t)MBUF_ROWS * 256];   // hmid hi
__device__ __nv_bfloat16 g_ML[(size_t)MBUF_ROWS * 256];   // hmid lo
#define WSLOT (2048 * 512)
__device__ __nv_bfloat16 g_WHb[6 * WSLOT];                // W hi, 6 slots
__device__ __nv_bfloat16 g_WLb[6 * WSLOT];                // W lo, 6 slots
__device__ float g_hpub[2 * BATCH * HID];                 // packed (hi,lo) bf16 pairs
__device__ float g_hT0[BATCH * HID], g_cT0[BATCH * HID];
__device__ float g_hT1[BATCH * HID], g_cT1[BATCH * HID];
__device__ float g_hTd[BATCH * HID], g_cTd[BATCH * HID];
__device__ unsigned g_bar[16];                            // 4 slots x 4 scans

// ---------------- helpers ----------------
__device__ __forceinline__ void bf16_split(float v, __nv_bfloat16& hi, __nv_bfloat16& lo) {
    hi = __float2bfloat16(v);
    lo = __float2bfloat16(v - __bfloat162float(hi));
}

__device__ __forceinline__ uint32_t smem_to_u32(const void* p) {
    uint32_t a;
    asm("{ .reg .u64 t; cvta.to.shared.u64 t, %1; cvt.u32.u64 %0, t; }" : "=r"(a) : "l"(p));
    return a;
}

// HMMA m16n8k16 bf16 (non-arch-gated PTX; runs on sm_103 base target)
__device__ __forceinline__ void mma16816(float* d, const uint32_t* a, const uint32_t* b) {
    asm volatile(
        "mma.sync.aligned.m16n8k16.row.col.f32.bf16.bf16.f32 "
        "{%0,%1,%2,%3}, {%4,%5,%6,%7}, {%8,%9}, {%0,%1,%2,%3};"
        : "+f"(d[0]), "+f"(d[1]), "+f"(d[2]), "+f"(d[3])
        : "r"(a[0]), "r"(a[1]), "r"(a[2]), "r"(a[3]), "r"(b[0]), "r"(b[1]));
}

// ldmatrix x4 (sm_75 PTX, non-gated)
__device__ __forceinline__ void ldsm4(uint32_t* r, uint32_t addr) {
    asm volatile("ldmatrix.sync.aligned.m8n8.x4.shared.b16 {%0,%1,%2,%3}, [%4];"
        : "=r"(r[0]), "=r"(r[1]), "=r"(r[2]), "=r"(r[3]) : "r"(addr));
}

// cp.async 16B (LDGSTS; sm_80 PTX, non-gated)
__device__ __forceinline__ void cpasync16(uint32_t s, const void* g) {
    asm volatile("cp.async.cg.shared.global [%0], [%1], 16;" :: "r"(s), "l"(g));
}
#define CP_COMMIT() asm volatile("cp.async.commit_group;" ::: "memory")
#define CP_WAIT1()  asm volatile("cp.async.wait_group 1;" ::: "memory")

// ---------------- small utility kernels ----------------
__global__ void reset_bar_kernel(unsigned* bar) {
    if (threadIdx.x < 16) bar[threadIdx.x] = 0u;
}

// padded-shifted input -> bf16 hi/lo, layout [b][t][192] (cols 176..191 zero)
__global__ void pad_shift_bf16_kernel(const float* __restrict__ src,
                                      __nv_bfloat16* __restrict__ dH,
                                      __nv_bfloat16* __restrict__ dL,
                                      int Tsrc, int Tpad, int Tcopy) {
    long n = (long)BATCH * Tpad * 192;
    long i = (long)blockIdx.x * blockDim.x + threadIdx.x;
    if (i >= n) return;
    int d = (int)(i % 192);
    long bt = i / 192;
    int t = (int)(bt % Tpad);
    int b = (int)(bt / Tpad);
    float v = (d < DIN && t > 0 && t <= Tcopy) ? src[((long)b * Tsrc + (t - 1)) * DIN + d] : 0.f;
    __nv_bfloat16 hi, lo; bf16_split(v, hi, lo);
    dH[i] = hi; dL[i] = lo;
}

// W (N x K fp32) -> WH/WL (Npad x kpad bf16, zero padded)
__global__ void conv_w_kernel(const float* __restrict__ W,
                              __nv_bfloat16* __restrict__ WH, __nv_bfloat16* __restrict__ WL,
                              int N, int K, int kpad, int Npad) {
    long n = (long)Npad * kpad;
    long i = (long)blockIdx.x * blockDim.x + threadIdx.x;
    if (i >= n) return;
    int row = (int)(i / kpad), c = (int)(i % kpad);
    float v = (row < N && c < K) ? W[(size_t)row * K + c] : 0.f;
    __nv_bfloat16 hi, lo; bf16_split(v, hi, lo);
    WH[i] = hi; WL[i] = lo;
}

__global__ void zero_t0_kernel(float* __restrict__ out) {
    int i = blockIdx.x * blockDim.x + threadIdx.x;
    if (i < BATCH * DIN) {
        int b = i / DIN, d = i % DIN;
        out[(size_t)b * 1024 * DIN + d] = 0.f;
    }
}

// ---------------- HMMA GEMM (128x128 tile, cp.async 2-stage, ldmatrix) -----
#define SOFF_AL  5120
#define SOFF_BH  10240
#define SOFF_BL  15360
#define STG_ELEMS 20480
#define MMA_SMEM_BYTES (2 * STG_ELEMS * 2)   // 81920

__global__ void __launch_bounds__(256, 2)
mma_gemm_kernel(const __nv_bfloat16* __restrict__ AH, const __nv_bfloat16* __restrict__ AL,
                const __nv_bfloat16* __restrict__ WH, const __nv_bfloat16* __restrict__ WL,
                int kpad, int nChunks,
                const float* __restrict__ b1, const float* __restrict__ b2,
                float* __restrict__ Cf, __nv_bfloat16* __restrict__ CH,
                __nv_bfloat16* __restrict__ CL,
                int ldC, int M, int Nreal, int relu, int remapT) {
    extern __shared__ __align__(16) __nv_bfloat16 smbuf[];
    const uint32_t sb = smem_to_u32(smbuf);

    const int tid  = threadIdx.x;
    const int wid  = tid >> 5, lane = tid & 31;
    const int g    = lane >> 2, tg = lane & 3;
    const int m0   = (wid & 3) * 32;
    const int n0   = (wid >> 2) * 64;
    const int row0 = blockIdx.y * 128;
    const int col0 = blockIdx.x * 128;

    const int lr0 = tid >> 2, lseg = tid & 3;   // loader: rows lr0, lr0+64

    // ldmatrix per-lane element offsets (element units, exclude kb and region)
    const int aoff = (m0 + (lane & 15)) * 40 + ((lane >> 4) << 3);
    const int boff = (n0 + ((lane & 7) + ((lane >> 4) << 3))) * 40
                   + (((lane >> 3) & 1) << 3);

    float d[2][8][4];
#pragma unroll
    for (int mi = 0; mi < 2; mi++)
#pragma unroll
        for (int ni = 0; ni < 8; ni++)
#pragma unroll
            for (int q = 0; q < 4; q++) d[mi][ni][q] = 0.f;

    auto load_chunk = [&](int ch, int stg) {
        const int kbase = ch * 32;
        const uint32_t base = sb + stg * (STG_ELEMS * 2);
#pragma unroll
        for (int i = 0; i < 2; i++) {
            int r = lr0 + i * 64;
            size_t ga = (size_t)(row0 + r) * kpad + kbase + lseg * 8;
            size_t gb = (size_t)(col0 + r) * kpad + kbase + lseg * 8;
            uint32_t so = base + (r * 40 + lseg * 8) * 2;
            cpasync16(so, AH + ga);
            cpasync16(so + SOFF_AL * 2, AL + ga);
            cpasync16(so + SOFF_BH * 2, WH + gb);
            cpasync16(so + SOFF_BL * 2, WL + gb);
        }
    };

    load_chunk(0, 0);
    CP_COMMIT();

    for (int ch = 0; ch < nChunks; ch++) {
        const int cur = ch & 1;
        if (ch + 1 < nChunks) load_chunk(ch + 1, cur ^ 1);
        CP_COMMIT();
        CP_WAIT1();
        __syncthreads();

        const uint32_t bufb = sb + cur * (STG_ELEMS * 2);

#pragma unroll
        for (int ks = 0; ks < 2; ks++) {
            const int kb = ks * 16;
            uint32_t aH[2][4], aL[2][4];
#pragma unroll
            for (int mi = 0; mi < 2; mi++) {
                uint32_t ad = bufb + (uint32_t)(aoff + mi * 16 * 40 + kb) * 2;
                ldsm4(aH[mi], ad);
                ldsm4(aL[mi], ad + SOFF_AL * 2);
            }
            uint32_t bH[8][2], bL[8][2];
#pragma unroll
            for (int p = 0; p < 4; p++) {
                uint32_t bd = bufb + SOFF_BH * 2 + (uint32_t)(boff + p * 16 * 40 + kb) * 2;
                uint32_t rH[4], rL[4];
                ldsm4(rH, bd);
                ldsm4(rL, bd + (SOFF_BL - SOFF_BH) * 2);
                bH[2 * p][0] = rH[0]; bH[2 * p][1] = rH[1];
                bH[2 * p + 1][0] = rH[2]; bH[2 * p + 1][1] = rH[3];
                bL[2 * p][0] = rL[0]; bL[2 * p][1] = rL[1];
                bL[2 * p + 1][0] = rL[2]; bL[2 * p + 1][1] = rL[3];
            }
#pragma unroll
            for (int ni = 0; ni < 8; ni++) {
#pragma unroll
                for (int mi = 0; mi < 2; mi++) {
                    mma16816(d[mi][ni], aH[mi], bH[ni]);
                    mma16816(d[mi][ni], aL[mi], bH[ni]);
                    mma16816(d[mi][ni], aH[mi], bL[ni]);
                }
            }
        }
        __syncthreads();
    }

    // epilogue: bias/relu, optional remap, fp32 and/or bf16 hi/lo stores
#pragma unroll
    for (int mi = 0; mi < 2; mi++) {
#pragma unroll
        for (int rr = 0; rr < 2; rr++) {
            int r = row0 + m0 + mi * 16 + g + rr * 8;
            if (r >= M) continue;
            size_t rowbase;
            if (remapT > 0) {
                int bb = r / remapT, tt = r - bb * remapT;
                rowbase = ((size_t)bb * (remapT + 1) + tt + 1) * (size_t)ldC;
            } else {
                rowbase = (size_t)r * ldC;
            }
#pragma unroll
            for (int ni = 0; ni < 8; ni++) {
#pragma unroll
                for (int cc = 0; cc < 2; cc++) {
                    int col = col0 + n0 + ni * 8 + 2 * tg + cc;
                    if (col >= Nreal) continue;
                    float v = d[mi][ni][rr * 2 + cc]
                            + (b1 ? __ldg(b1 + col) : 0.f) + (b2 ? __ldg(b2 + col) : 0.f);
                    if (relu) v = fmaxf(v, 0.f);
                    if (Cf) Cf[rowbase + col] = v;
                    if (CH) {
                        __nv_bfloat16 hi, lo; bf16_split(v, hi, lo);
                        CH[rowbase + col] = hi;
                        CL[rowbase + col] = lo;
                    }
                }
            }
        }
    }
}

// ---------------- persistent LSTM scan (round-15, unchanged) ---------------
#define SW_K     520
#define SOFF_WL2 (64 * SW_K)               // 33280
#define SOFF_HH  (2 * 64 * SW_K)           // 66560
#define SOFF_HL  (SOFF_HH + 16 * SW_K)     // 74880
#define SCAN_BF16_ELEMS (SOFF_HL + 16 * SW_K)   // 83200
#define SCAN_RED_FLOATS (8 * 16 * 66)      // 8448
#define SCAN_SMEM_BYTES (SCAN_BF16_ELEMS * 2 + SCAN_RED_FLOATS * 4)  // 200192

__device__ __forceinline__ float sigf(float x) { return 1.f / (1.f + expf(-x)); }

__device__ __forceinline__ void group_barrier(unsigned* bar, int bg, unsigned target) {
    __threadfence();
    __syncthreads();
    if (threadIdx.x == 0) {
        atomicAdd(&bar[bg], 1u);
        while (atomicAdd(&bar[bg], 0u) < target) { __nanosleep(64); }
        __threadfence();
    }
    __syncthreads();
}

__global__ void __launch_bounds__(256, 1)
lstm_scan_kernel(const float* __restrict__ gx, const float* __restrict__ Whh,
                 const float* __restrict__ h0, const float* __restrict__ c0,
                 __nv_bfloat16* __restrict__ hsH, __nv_bfloat16* __restrict__ hsL,
                 float* __restrict__ hT_out, float* __restrict__ cT_out,
                 float* __restrict__ hpub, unsigned* __restrict__ bar, int T) {
    extern __shared__ __align__(16) __nv_bfloat16 sm[];
    __nv_bfloat16* sWH = sm;                 // [64][520] (used once)
    __nv_bfloat16* sWL = sm + SOFF_WL2;      // [64][520] (used once)
    __nv_bfloat16* sHH = sm + SOFF_HH;       // [16][520]
    __nv_bfloat16* sHL = sm + SOFF_HL;       // [16][520]
    float* red = (float*)(sm + SCAN_BF16_ELEMS);  // [8][16][66]

    uint32_t* hpub32 = (uint32_t*)hpub;      // packed (hi | lo<<16) bf16 pairs

    const int tid = threadIdx.x;
    const int bg = blockIdx.x >> 5;
    const int ht = blockIdx.x & 31;
    const int B0 = bg * 16;
    const int J0 = ht * 16;
    const int w = tid >> 5;
    const int lane = tid & 31;
    const int g = lane >> 2, tg = lane & 3;

    // ---- load + split Whh slice into smem (once); n = gate*16 + j ----
    for (int idx = tid; idx < 64 * 512; idx += 256) {
        int n = idx >> 9, k = idx & 511;
        float v = Whh[(size_t)((n >> 4) * 512 + J0 + (n & 15)) * 512 + k];
        __nv_bfloat16 hi, lo; bf16_split(v, hi, lo);
        sWH[n * SW_K + k] = hi;
        sWL[n * SW_K + k] = lo;
    }

    // ---- init states ----
    const int ub = tid >> 4;            // batch within tile (0..15)
    const int uj = tid & 15;            // hidden within tile (0..15)
    float cval = c0 ? c0[(B0 + ub) * 512 + J0 + uj] : 0.f;
    float hval = h0 ? h0[(B0 + ub) * 512 + J0 + uj] : 0.f;
    {
        __nv_bfloat16 hi, lo; bf16_split(hval, hi, lo);
        uint32_t hp = (uint32_t)__bfloat16_as_ushort(hi)
                    | ((uint32_t)__bfloat16_as_ushort(lo) << 16);
        hpub32[32768 + (B0 + ub) * 512 + J0 + uj] = hp;   // parity-1 feeds t=0
    }

    unsigned nbar = 1;
    group_barrier(bar, bg, nbar * 32);   // covers weight-fill visibility too

    // ---- hoist B (weight) fragments into registers: [ks][ni][2] ----
    uint32_t rbH[4][8][2], rbL[4][8][2];
#pragma unroll
    for (int ks = 0; ks < 4; ks++) {
        const int kb = w * 64 + ks * 16;
#pragma unroll
        for (int ni = 0; ni < 8; ni++) {
            int r = ni * 8 + g;
            rbH[ks][ni][0] = *(const uint32_t*)&sWH[r * SW_K + kb + 2 * tg];
            rbH[ks][ni][1] = *(const uint32_t*)&sWH[r * SW_K + kb + 2 * tg + 8];
            rbL[ks][ni][0] = *(const uint32_t*)&sWL[r * SW_K + kb + 2 * tg];
            rbL[ks][ni][1] = *(const uint32_t*)&sWL[r * SW_K + kb + 2 * tg + 8];
        }
    }

    const int p1b = tid & 15;
    const int p1k = tid >> 4;

    const float* gxrow = gx + ((size_t)(B0 + ub) * T) * G4 + J0 + uj;
    __nv_bfloat16* hH = hsH ? hsH + ((size_t)(B0 + ub) * T) * 512 + J0 + uj : nullptr;
    __nv_bfloat16* hL = hsL ? hsL + ((size_t)(B0 + ub) * T) * 512 + J0 + uj : nullptr;

    for (int t = 0; t < T; ++t) {
        float pgi = gxrow[0], pgf = gxrow[512], pgg = gxrow[1024], pgo = gxrow[1536];

        const uint32_t* hsrc = hpub32 + (((t + 1) & 1) << 15);

        // phase 1: load packed h pairs, de-interleave hi/lo via PRMT
#pragma unroll
        for (int i = 0; i < 8; ++i) {
            int kq = p1k + (i << 4);                  // uint4 index 0..127
            uint4 hv = __ldcg((const uint4*)(hsrc + (B0 + p1b) * 512 + (kq << 2)));
            int base = p1b * SW_K + (kq << 2);
            *(uint32_t*)&sHH[base]     = __byte_perm(hv.x, hv.y, 0x5410);
            *(uint32_t*)&sHL[base]     = __byte_perm(hv.x, hv.y, 0x7632);
            *(uint32_t*)&sHH[base + 2] = __byte_perm(hv.z, hv.w, 0x5410);
            *(uint32_t*)&sHL[base + 2] = __byte_perm(hv.z, hv.w, 0x7632);
        }
        __syncthreads();

        // phase 2: HMMA m16 x n64 x k64, weights from registers
        float c[8][4];
#pragma unroll
        for (int ni = 0; ni < 8; ni++)
#pragma unroll
            for (int q = 0; q < 4; q++) c[ni][q] = 0.f;

        const int kb0 = w * 64;
#pragma unroll
        for (int ks = 0; ks < 4; ks++) {
            const int kb = kb0 + ks * 16;
            uint32_t aH[4], aL[4];
            aH[0] = *(const uint32_t*)&sHH[g * SW_K + kb + 2 * tg];
            aH[1] = *(const uint32_t*)&sHH[(g + 8) * SW_K + kb + 2 * tg];
            aH[2] = *(const uint32_t*)&sHH[g * SW_K + kb + 2 * tg + 8];
            aH[3] = *(const uint32_t*)&sHH[(g + 8) * SW_K + kb + 2 * tg + 8];
            aL[0] = *(const uint32_t*)&sHL[g * SW_K + kb + 2 * tg];
            aL[1] = *(const uint32_t*)&sHL[(g + 8) * SW_K + kb + 2 * tg];
            aL[2] = *(const uint32_t*)&sHL[g * SW_K + kb + 2 * tg + 8];
            aL[3] = *(const uint32_t*)&sHL[(g + 8) * SW_K + kb + 2 * tg + 8];
#pragma unroll
            for (int ni = 0; ni < 8; ni++) {
                mma16816(c[ni], aH, rbH[ks][ni]);
                mma16816(c[ni], aL, rbH[ks][ni]);
                mma16816(c[ni], aH, rbL[ks][ni]);
            }
        }

        // phase 3: fragments -> red[w][m][n] (pad 66)
#pragma unroll
        for (int ni = 0; ni < 8; ni++) {
            int nn = ni * 8 + 2 * tg;
            float2 v01 = make_float2(c[ni][0], c[ni][1]);
            float2 v23 = make_float2(c[ni][2], c[ni][3]);
            *(float2*)&red[w * 1056 + g * 66 + nn] = v01;
            *(float2*)&red[w * 1056 + (g + 8) * 66 + nn] = v23;
        }
        __syncthreads();

        // phase 4: reduce 8 k-slices, add gx, LSTM cell (thread = (ub,uj))
        float gsum[4];
#pragma unroll
        for (int gt = 0; gt < 4; gt++) {
            float v = 0.f;
#pragma unroll
            for (int s2 = 0; s2 < 8; s2++)
                v += red[s2 * 1056 + ub * 66 + gt * 16 + uj];
            gsum[gt] = v;
        }
        float gi = gsum[0] + pgi, gf = gsum[1] + pgf;
        float gg = gsum[2] + pgg, go = gsum[3] + pgo;

        float ig = sigf(gi), fg = sigf(gf), og_ = sigf(go), gt_ = tanhf(gg);
        cval = fg * cval + ig * gt_;
        hval = og_ * tanhf(cval);

        __nv_bfloat16 hi, lo; bf16_split(hval, hi, lo);
        uint32_t hp = (uint32_t)__bfloat16_as_ushort(hi)
                    | ((uint32_t)__bfloat16_as_ushort(lo) << 16);
        hpub32[((t & 1) << 15) + (B0 + ub) * 512 + J0 + uj] = hp;
        if (hH) { *hH = hi; *hL = lo; hH += 512; hL += 512; }
        gxrow += G4;

        ++nbar;
        group_barrier(bar, bg, nbar * 32);
    }

    hT_out[(B0 + ub) * 512 + J0 + uj] = hval;
    cT_out[(B0 + ub) * 512 + J0 + uj] = cval;
}

// ---------------- host orchestration ----------------
static __nv_bfloat16 *s_AH, *s_AL, *s_BH, *s_BL, *s_YH, *s_YL, *s_MH, *s_ML, *s_WH, *s_WL;

static void launch_mma_s(cudaStream_t st,
                         const __nv_bfloat16* AH, const __nv_bfloat16* AL,
                         const __nv_bfloat16* WHp, const __nv_bfloat16* WLp,
                         int kpad, const float* b1, const float* b2,
                         float* Cf, __nv_bfloat16* CH, __nv_bfloat16* CL,
                         int ldC, int M, int Nreal, int relu, int remapT) {
    int mt = (M + 127) / 128;
    int nt = (Nreal + 127) / 128;
    int nChunks = kpad / 32;
    mma_gemm_kernel<<<dim3(nt, mt), 256, MMA_SMEM_BYTES, st>>>(
        AH, AL, WHp, WLp, kpad, nChunks, b1, b2, Cf, CH, CL, ldC, M, Nreal, relu, remapT);
}

static void launch_convw_s(cudaStream_t st, const float* W, int N, int K, int kpad,
                           __nv_bfloat16* WHp, __nv_bfloat16* WLp) {
    int Npad = ((N + 63) / 64) * 64;
    long n = (long)Npad * kpad;
    conv_w_kernel<<<(int)((n + 255) / 256), 256, 0, st>>>(W, WHp, WLp, N, K, kpad, Npad);
}

extern "C" void kernel_launch(void* const* d_in, const int* in_sizes, int n_in,
                              void* d_out, int out_size) {
    (void)in_sizes; (void)n_in; (void)out_size;
    const float* x     = (const float*)d_in[0];
    const float* y     = (const float*)d_in[1];
    const float* eWih0 = (const float*)d_in[2];
    const float* eWhh0 = (const float*)d_in[3];
    const float* ebih0 = (const float*)d_in[4];
    const float* ebhh0 = (const float*)d_in[5];
    const float* eWih1 = (const float*)d_in[6];
    const float* eWhh1 = (const float*)d_in[7];
    const float* ebih1 = (const float*)d_in[8];
    const float* ebhh1 = (const float*)d_in[9];
    const float* dWih0 = (const float*)d_in[10];
    const float* dWhh0 = (const float*)d_in[11];
    const float* dbih0 = (const float*)d_in[12];
    const float* dbhh0 = (const float*)d_in[13];
    const float* dWih1 = (const float*)d_in[14];
    const float* dWhh1 = (const float*)d_in[15];
    const float* dbih1 = (const float*)d_in[16];
    const float* dbhh1 = (const float*)d_in[17];
    const float* clsW1 = (const float*)d_in[18];
    const float* clsb1 = (const float*)d_in[19];
    const float* clsW2 = (const float*)d_in[20];
    const float* clsb2 = (const float*)d_in[21];
    float* out = (float*)d_out;

    // stream/event statics: created on the first (uncaptured) correctness call
    static cudaStream_t sB = nullptr;
    static cudaEvent_t evFork = nullptr, evGx2 = nullptr, evS0 = nullptr,
                       evE1 = nullptr, evD0 = nullptr, evD1 = nullptr, evW = nullptr;
    if (sB == nullptr) {
        cudaStreamCreateWithFlags(&sB, cudaStreamNonBlocking);
        cudaEventCreateWithFlags(&evFork, cudaEventDisableTiming);
        cudaEventCreateWithFlags(&evGx2,  cudaEventDisableTiming);
        cudaEventCreateWithFlags(&evS0,   cudaEventDisableTiming);
        cudaEventCreateWithFlags(&evE1,   cudaEventDisableTiming);
        cudaEventCreateWithFlags(&evD0,   cudaEventDisableTiming);
        cudaEventCreateWithFlags(&evD1,   cudaEventDisableTiming);
        cudaEventCreateWithFlags(&evW,    cudaEventDisableTiming);
    }

    float *gx, *gx2, *hpub, *hT0, *cT0, *hT1, *cT1, *hTd, *cTd;
    unsigned* bar;
    cudaGetSymbolAddress((void**)&gx,   g_gx);
    cudaGetSymbolAddress((void**)&gx2,  g_gx2);
    cudaGetSymbolAddress((void**)&hpub, g_hpub);
    cudaGetSymbolAddress((void**)&hT0,  g_hT0);
    cudaGetSymbolAddress((void**)&cT0,  g_cT0);
    cudaGetSymbolAddress((void**)&hT1,  g_hT1);
    cudaGetSymbolAddress((void**)&cT1,  g_cT1);
    cudaGetSymbolAddress((void**)&hTd,  g_hTd);
    cudaGetSymbolAddress((void**)&cTd,  g_cTd);
    cudaGetSymbolAddress((void**)&bar,  g_bar);
    cudaGetSymbolAddress((void**)&s_AH, g_AH);
    cudaGetSymbolAddress((void**)&s_AL, g_AL);
    cudaGetSymbolAddress((void**)&s_BH, g_BH);
    cudaGetSymbolAddress((void**)&s_BL, g_BL);
    cudaGetSymbolAddress((void**)&s_YH, g_YH);
    cudaGetSymbolAddress((void**)&s_YL, g_YL);
    cudaGetSymbolAddress((void**)&s_MH, g_MH);
    cudaGetSymbolAddress((void**)&s_ML, g_ML);
    cudaGetSymbolAddress((void**)&s_WH, g_WHb);
    cudaGetSymbolAddress((void**)&s_WL, g_WLb);

    cudaFuncSetAttribute(lstm_scan_kernel,
                         cudaFuncAttributeMaxDynamicSharedMemorySize, SCAN_SMEM_BYTES);
    cudaFuncSetAttribute(mma_gemm_kernel,
                         cudaFuncAttributeMaxDynamicSharedMemorySize, MMA_SMEM_BYTES);

    const int ME  = MROWS_MAX;   // 65600
    const int MDN = MD_ROWS;     // 65472

    // W slots: 0=eWih0, 1=dWih0, 2=eWih1, 3=dWih1, 4=clsW1, 5=clsW2
    __nv_bfloat16 *WH0 = s_WH,             *WL0 = s_WL;
    __nv_bfloat16 *WH1 = s_WH + 1 * WSLOT, *WL1 = s_WL + 1 * WSLOT;
    __nv_bfloat16 *WH2 = s_WH + 2 * WSLOT, *WL2 = s_WL + 2 * WSLOT;
    __nv_bfloat16 *WH3 = s_WH + 3 * WSLOT, *WL3 = s_WL + 3 * WSLOT;
    __nv_bfloat16 *WH4 = s_WH + 4 * WSLOT, *WL4 = s_WL + 4 * WSLOT;
    __nv_bfloat16 *WH5 = s_WH + 5 * WSLOT, *WL5 = s_WL + 5 * WSLOT;

    // -------- stream A: barrier reset + encoder L0 --------
    reset_bar_kernel<<<1, 32>>>(bar);
    {
        long n = (long)BATCH * T_ENC * 192;
        pad_shift_bf16_kernel<<<(int)((n + 255) / 256), 256>>>(x, s_AH, s_AL, 1024, T_ENC, 1024);
    }
    launch_convw_s(0, eWih0, G4, DIN, 192, WH0, WL0);
    launch_mma_s(0, s_AH, s_AL, WH0, WL0, 192, ebih0, ebhh0,
                 gx, nullptr, nullptr, G4, ME, G4, 0, 0);
    cudaEventRecord(evFork, 0);

    // -------- stream B: dec input prep + weight conversions + dec L0 gemm ---
    cudaStreamWaitEvent(sB, evFork, 0);
    zero_t0_kernel<<<(BATCH * DIN + 255) / 256, 256, 0, sB>>>(out);
    {
        long n = (long)BATCH * T_DEC * 192;
        pad_shift_bf16_kernel<<<(int)((n + 255) / 256), 256, 0, sB>>>(y, s_YH, s_YL, 1024, T_DEC, 1022);
    }
    launch_convw_s(sB, dWih0, G4, DIN, 192, WH1, WL1);
    launch_convw_s(sB, eWih1, G4, HID, 512, WH2, WL2);
    launch_convw_s(sB, dWih1, G4, HID, 512, WH3, WL3);
    launch_convw_s(sB, clsW1, 256, HID, 512, WH4, WL4);
    launch_convw_s(sB, clsW2, DIN, 256, 256, WH5, WL5);
    cudaEventRecord(evW, sB);
    launch_mma_s(sB, s_YH, s_YL, WH1, WL1, 192, dbih0, dbhh0,
                 gx2, nullptr, nullptr, G4, MDN, G4, 0, 0);
    cudaEventRecord(evGx2, sB);

    // -------- stream A: enc scan 0 (writes AH/AL enc hidden seq) --------
    lstm_scan_kernel<<<128, 256, SCAN_SMEM_BYTES>>>(gx, eWhh0, nullptr, nullptr,
                                                    s_AH, s_AL, hT0, cT0, hpub, bar + 0, T_ENC);
    cudaEventRecord(evS0, 0);

    // -------- stream B: enc L1 gemm (overlaps dec scan 0 on spare SMs) ------
    cudaStreamWaitEvent(sB, evS0, 0);
    launch_mma_s(sB, s_AH, s_AL, WH2, WL2, 512, ebih1, ebhh1,
                 gx, nullptr, nullptr, G4, ME, G4, 0, 0);
    cudaEventRecord(evE1, sB);

    // -------- stream A: dec scan 0 (needs gx2 + hT0; writes BH/BL) ---------
    cudaStreamWaitEvent(0, evGx2, 0);
    lstm_scan_kernel<<<128, 256, SCAN_SMEM_BYTES>>>(gx2, dWhh0, hT0, cT0,
                                                    s_BH, s_BL, hTd, cTd, hpub, bar + 8, T_DEC);
    cudaEventRecord(evD0, 0);

    // -------- stream B: dec L1 gemm (overlaps enc scan 1 on spare SMs) ------
    cudaStreamWaitEvent(sB, evD0, 0);
    launch_mma_s(sB, s_BH, s_BL, WH3, WL3, 512, dbih1, dbhh1,
                 gx2, nullptr, nullptr, G4, MDN, G4, 0, 0);
    cudaEventRecord(evD1, sB);

    // -------- stream A: enc scan 1 (needs enc L1 gx) --------
    cudaStreamWaitEvent(0, evE1, 0);
    lstm_scan_kernel<<<128, 256, SCAN_SMEM_BYTES>>>(gx, eWhh1, nullptr, nullptr,
                                                    nullptr, nullptr, hT1, cT1, hpub, bar + 4, T_ENC);

    // -------- stream A: dec scan 1 (needs dec L1 gx2 + hT1; writes AH/AL) ---
    cudaStreamWaitEvent(0, evD1, 0);
    lstm_scan_kernel<<<128, 256, SCAN_SMEM_BYTES>>>(gx2, dWhh1, hT1, cT1,
                                                    s_AH, s_AL, hTd, cTd, hpub, bar + 12, T_DEC);

    // -------- classifier --------
    cudaStreamWaitEvent(0, evW, 0);
    launch_mma_s(0, s_AH, s_AL, WH4, WL4, 512, clsb1, nullptr,
                 nullptr, s_MH, s_ML, 256, MDN, 256, 1, 0);
    launch_mma_s(0, s_MH, s_ML, WH5, WL5, 256, clsb2, nullptr,
                 out, nullptr, nullptr, DIN, MDN, DIN, 0, T_DEC);
}